// round 9
// baseline (speedup 1.0000x reference)
#include <cuda_runtime.h>
#include <math.h>

// ---------------- problem constants ----------------
#define B_   4
#define F_   256
#define N0_  128
#define N1_  128
#define N_   256        // nodes per graph
#define BN_  1024       // total nodes
#define L_   3

#define ASTR 20         // smem stride for A tile (64 x 16), conflict-free + 16B aligned
#define BSTR 72         // smem stride for B tile (16 x 64), conflict-free + 16B aligned

// ---------------- scratch (device globals; no allocation) ----------------
__device__ float g_x[BN_ * F_];
__device__ float g_H[2 * BN_ * F_];
__device__ float g_qs[2 * BN_];
__device__ float g_ks[2 * BN_];
__device__ float g_alpha[B_ * N_ * N_];
__device__ float g_msg1[BN_ * F_];
__device__ float g_msg2[BN_ * F_];
__device__ float g_lwT[2 * F_ * F_];
__device__ float g_sum[F_];
__device__ float g_sum2[F_];
__device__ float g_mu[F_];
__device__ float g_rstd[F_];

// ---------------- tf32 helpers ----------------
__device__ __forceinline__ unsigned f2tf(float f) {
    unsigned u;
    asm("cvt.rna.tf32.f32 %0, %1;" : "=r"(u) : "f"(f));
    return u;
}

__device__ __forceinline__ void mma8(float* d, const unsigned* a, const unsigned* b) {
    asm volatile(
        "mma.sync.aligned.m16n8k8.row.col.f32.tf32.tf32.f32 "
        "{%0,%1,%2,%3},{%4,%5,%6,%7},{%8,%9},{%0,%1,%2,%3};\n"
        : "+f"(d[0]), "+f"(d[1]), "+f"(d[2]), "+f"(d[3])
        : "r"(a[0]), "r"(a[1]), "r"(a[2]), "r"(a[3]), "r"(b[0]), "r"(b[1]));
}

// 64x64 block tile, 4 warps (warp tile 32x32 = 2 m-frags x 4 n-frags), BK=16
__device__ __forceinline__ void compute_bk(const unsigned* As, const unsigned* Bs,
                                           float acc[2][4][4], int lane, int wm, int wn) {
    int g = lane >> 2, tg = lane & 3;
#pragma unroll
    for (int s = 0; s < 2; s++) {
        int kb = s * 8;
        unsigned a[2][4], b[4][2];
#pragma unroll
        for (int i = 0; i < 2; i++) {
            int r0 = wm + i * 16 + g;
            a[i][0] = As[r0 * ASTR + kb + tg];
            a[i][1] = As[(r0 + 8) * ASTR + kb + tg];
            a[i][2] = As[r0 * ASTR + kb + tg + 4];
            a[i][3] = As[(r0 + 8) * ASTR + kb + tg + 4];
        }
#pragma unroll
        for (int j = 0; j < 4; j++) {
            b[j][0] = Bs[(kb + tg) * BSTR + wn + j * 8 + g];
            b[j][1] = Bs[(kb + tg + 4) * BSTR + wn + j * 8 + g];
        }
#pragma unroll
        for (int i = 0; i < 2; i++)
#pragma unroll
            for (int j = 0; j < 4; j++) mma8(acc[i][j], a[i], b[j]);
    }
}

__device__ __forceinline__ void store_tiles(unsigned* Asm, unsigned* Bsm,
                                            const float4* ra, const float4* rb, int t) {
#pragma unroll
    for (int u = 0; u < 2; u++) {
        int idx = t * 2 + u;
        {
            int row = idx >> 2, c4 = (idx & 3) * 4;
            uint4 w = make_uint4(f2tf(ra[u].x), f2tf(ra[u].y), f2tf(ra[u].z), f2tf(ra[u].w));
            *(uint4*)&Asm[row * ASTR + c4] = w;
        }
        {
            int row = idx >> 4, c4 = (idx & 15) * 4;
            uint4 w = make_uint4(f2tf(rb[u].x), f2tf(rb[u].y), f2tf(rb[u].z), f2tf(rb[u].w));
            *(uint4*)&Bsm[row * BSTR + c4] = w;
        }
    }
}

// ---------------- pack (+zero accumulators for layer 0) ----------------
__global__ void pack_kernel(const float* __restrict__ d0, const float* __restrict__ d1) {
    int b = blockIdx.x >> 8;
    int n = blockIdx.x & 255;
    int f = threadIdx.x;
    float v;
    if (n < N0_) v = d0[(b * F_ + f) * N0_ + n];
    else         v = d1[(b * F_ + f) * N1_ + (n - N0_)];
    g_x[(b * N_ + n) * F_ + f] = v;
    if (blockIdx.x < 18) {
        int zi = blockIdx.x * 256 + f;
        if (zi < 2048)       g_qs[zi] = 0.f;
        else if (zi < 4096)  g_ks[zi - 2048] = 0.f;
        else if (zi < 4352)  g_sum[zi - 4096] = 0.f;
        else                 g_sum2[zi - 4352] = 0.f;
    }
}

// ---------------- H = x @ W[r], fused q/k scores. grid (4,16,2) x 128 ----------------
__global__ __launch_bounds__(128) void gemm_H_mma(const float* __restrict__ W,
                                                  const float* __restrict__ q,
                                                  const float* __restrict__ kvec) {
    int r = blockIdx.z;
    const float* Bp = W + r * F_ * F_;
    float* C = g_H + (size_t)r * BN_ * F_;
    int m0 = blockIdx.y * 64, n0 = blockIdx.x * 64;
    __shared__ unsigned Asm[64 * ASTR], Bsm[16 * BSTR];
    int t = threadIdx.x, lane = t & 31, warp = t >> 5;
    int wm = (warp >> 1) * 32, wn = (warp & 1) * 32;
    float acc[2][4][4] = {};
    float4 ra[2], rb[2];
#pragma unroll
    for (int u = 0; u < 2; u++) {
        int idx = t * 2 + u;
        { int row = idx >> 2, c4 = (idx & 3) * 4; ra[u] = *(const float4*)&g_x[(m0 + row) * F_ + c4]; }
        { int row = idx >> 4, c4 = (idx & 15) * 4; rb[u] = *(const float4*)&Bp[row * F_ + n0 + c4]; }
    }
    for (int k0 = 0; k0 < F_; k0 += 16) {
        store_tiles(Asm, Bsm, ra, rb, t);
        __syncthreads();
        int kn = k0 + 16;
        if (kn < F_) {
#pragma unroll
            for (int u = 0; u < 2; u++) {
                int idx = t * 2 + u;
                { int row = idx >> 2, c4 = (idx & 3) * 4; ra[u] = *(const float4*)&g_x[(m0 + row) * F_ + kn + c4]; }
                { int row = idx >> 4, c4 = (idx & 15) * 4; rb[u] = *(const float4*)&Bp[(kn + row) * F_ + n0 + c4]; }
            }
        }
        compute_bk(Asm, Bsm, acc, lane, wm, wn);
        __syncthreads();
    }
    int g = lane >> 2, tg = lane & 3;
#pragma unroll
    for (int i = 0; i < 2; i++)
#pragma unroll
        for (int j = 0; j < 4; j++) {
            int row = m0 + wm + i * 16 + g, col = n0 + wn + j * 8 + tg * 2;
            *(float2*)&C[row * F_ + col] = make_float2(acc[i][j][0], acc[i][j][1]);
            *(float2*)&C[(row + 8) * F_ + col] = make_float2(acc[i][j][2], acc[i][j][3]);
        }
    // fused per-node q/k scores (partial over this block's 64 cols)
    float2 qv[4], kv[4];
#pragma unroll
    for (int j = 0; j < 4; j++) {
        int col = n0 + wn + j * 8 + tg * 2;
        qv[j] = *(const float2*)&q[col];
        kv[j] = *(const float2*)&kvec[col];
    }
#pragma unroll
    for (int i = 0; i < 2; i++) {
        float qp0 = 0, qp1 = 0, kp0 = 0, kp1 = 0;
#pragma unroll
        for (int j = 0; j < 4; j++) {
            qp0 += acc[i][j][0] * qv[j].x + acc[i][j][1] * qv[j].y;
            qp1 += acc[i][j][2] * qv[j].x + acc[i][j][3] * qv[j].y;
            kp0 += acc[i][j][0] * kv[j].x + acc[i][j][1] * kv[j].y;
            kp1 += acc[i][j][2] * kv[j].x + acc[i][j][3] * kv[j].y;
        }
#pragma unroll
        for (int o = 1; o < 4; o <<= 1) {
            qp0 += __shfl_xor_sync(0xffffffffu, qp0, o);
            qp1 += __shfl_xor_sync(0xffffffffu, qp1, o);
            kp0 += __shfl_xor_sync(0xffffffffu, kp0, o);
            kp1 += __shfl_xor_sync(0xffffffffu, kp1, o);
        }
        if (tg == 0) {
            int row = m0 + wm + i * 16 + g;
            atomicAdd(&g_qs[r * BN_ + row], qp0);
            atomicAdd(&g_qs[r * BN_ + row + 8], qp1);
            atomicAdd(&g_ks[r * BN_ + row], kp0);
            atomicAdd(&g_ks[r * BN_ + row + 8], kp1);
        }
    }
}

// ---------------- attention weights: one warp per dst node ----------------
__global__ void alpha_kernel() {
    int warp = (blockIdx.x * blockDim.x + threadIdx.x) >> 5;
    int lane = threadIdx.x & 31;
    int g = warp >> 8;
    int d = warp & 255;
    int dc = d >> 7;
    int nd = g * N_ + d;
    float qs0 = g_qs[nd];
    float qs1 = g_qs[BN_ + nd];
    float l[8];
    float mx = -INFINITY;
#pragma unroll
    for (int j = 0; j < 8; j++) {
        int s = j * 32 + lane;
        int r = (s >> 7) ^ dc;
        float ks = g_ks[r * BN_ + g * N_ + s];
        float qv = r ? qs1 : qs0;
        float v = qv + ks;
        v = v >= 0.0f ? v : 0.2f * v;
        if (s == d) v = -INFINITY;
        l[j] = v;
        mx = fmaxf(mx, v);
    }
#pragma unroll
    for (int o = 16; o; o >>= 1) mx = fmaxf(mx, __shfl_xor_sync(0xffffffffu, mx, o));
    float sum = 0.0f;
#pragma unroll
    for (int j = 0; j < 8; j++) { l[j] = expf(l[j] - mx); sum += l[j]; }
#pragma unroll
    for (int o = 16; o; o >>= 1) sum += __shfl_xor_sync(0xffffffffu, sum, o);
    float inv = 1.0f / (sum + 1e-16f);
#pragma unroll
    for (int j = 0; j < 8; j++) g_alpha[nd * N_ + j * 32 + lane] = l[j] * inv;
}

// ---------------- attention aggregation GEMM, relu(+conv_b). grid (4,2,8) x 128 ----------------
__global__ __launch_bounds__(128) void attn_gemm_mma(const float* __restrict__ convb) {
    int z = blockIdx.z;
    int gg = z >> 1, dc = z & 1;
    int m0 = blockIdx.y * 64, n0 = blockIdx.x * 64;
    const float* A = g_alpha + (size_t)(gg * N_ + dc * 128) * N_;
    float* C = g_msg1 + (size_t)(gg * N_ + dc * 128) * F_;
    __shared__ unsigned Asm[64 * ASTR], Bsm[16 * BSTR];
    int t = threadIdx.x, lane = t & 31, warp = t >> 5;
    int wm = (warp >> 1) * 32, wn = (warp & 1) * 32;
    float acc[2][4][4] = {};
    float4 ra[2], rb[2];
    auto loadg = [&](int k0) {
#pragma unroll
        for (int u = 0; u < 2; u++) {
            int idx = t * 2 + u;
            { int row = idx >> 2, c4 = (idx & 3) * 4; ra[u] = *(const float4*)&A[(m0 + row) * N_ + k0 + c4]; }
            {
                int row = idx >> 4, c4 = (idx & 15) * 4;
                int s = k0 + row;
                int rel = (s >> 7) ^ dc;
                rb[u] = *(const float4*)&g_H[((size_t)rel * BN_ + gg * N_ + s) * F_ + n0 + c4];
            }
        }
    };
    loadg(0);
    for (int k0 = 0; k0 < N_; k0 += 16) {
        store_tiles(Asm, Bsm, ra, rb, t);
        __syncthreads();
        if (k0 + 16 < N_) loadg(k0 + 16);
        compute_bk(Asm, Bsm, acc, lane, wm, wn);
        __syncthreads();
    }
    int g = lane >> 2, tg = lane & 3;
#pragma unroll
    for (int i = 0; i < 2; i++)
#pragma unroll
        for (int j = 0; j < 4; j++) {
            int row = m0 + wm + i * 16 + g, col = n0 + wn + j * 8 + tg * 2;
            float b0 = convb[col], b1 = convb[col + 1];
            float v0 = fmaxf(acc[i][j][0] + b0, 0.f), v1 = fmaxf(acc[i][j][1] + b1, 0.f);
            float v2 = fmaxf(acc[i][j][2] + b0, 0.f), v3 = fmaxf(acc[i][j][3] + b1, 0.f);
            *(float2*)&C[row * F_ + col] = make_float2(v0, v1);
            *(float2*)&C[(row + 8) * F_ + col] = make_float2(v2, v3);
        }
}

// ---------------- transpose lin_w [256 o][512 k] -> g_lwT [512 k][256 o] ----------------
__global__ void transpose_lw(const float* __restrict__ lw) {
    __shared__ float tt[32][33];
    int k0 = blockIdx.x * 32, o0 = blockIdx.y * 32;
    int tx = threadIdx.x, ty = threadIdx.y;
    for (int i = ty; i < 32; i += 8) tt[i][tx] = lw[(o0 + i) * (2 * F_) + k0 + tx];
    __syncthreads();
    for (int i = ty; i < 32; i += 8) g_lwT[(k0 + i) * F_ + o0 + tx] = tt[tx][i];
}

// ---------------- msg2 = [x, msg1] @ lwT + lin_b, fused BN partial sums. grid (4,16) x 128 ----------------
__global__ __launch_bounds__(128) void lin_gemm_mma(const float* __restrict__ linb) {
    int m0 = blockIdx.y * 64, n0 = blockIdx.x * 64;
    __shared__ unsigned Asm[64 * ASTR], Bsm[16 * BSTR];
    int t = threadIdx.x, lane = t & 31, warp = t >> 5;
    int wm = (warp >> 1) * 32, wn = (warp & 1) * 32;
    float acc[2][4][4] = {};
    float4 ra[2], rb[2];
    auto loadg = [&](int k0) {
        const float* Abase = (k0 < F_) ? g_x : g_msg1;
        int kk = (k0 < F_) ? k0 : k0 - F_;
#pragma unroll
        for (int u = 0; u < 2; u++) {
            int idx = t * 2 + u;
            { int row = idx >> 2, c4 = (idx & 3) * 4; ra[u] = *(const float4*)&Abase[(m0 + row) * F_ + kk + c4]; }
            { int row = idx >> 4, c4 = (idx & 15) * 4; rb[u] = *(const float4*)&g_lwT[(k0 + row) * F_ + n0 + c4]; }
        }
    };
    loadg(0);
    for (int k0 = 0; k0 < 2 * F_; k0 += 16) {
        store_tiles(Asm, Bsm, ra, rb, t);
        __syncthreads();
        if (k0 + 16 < 2 * F_) loadg(k0 + 16);
        compute_bk(Asm, Bsm, acc, lane, wm, wn);
        __syncthreads();
    }
    int g = lane >> 2, tg = lane & 3;
    float s0[4], s1[4], q0[4], q1[4];
#pragma unroll
    for (int j = 0; j < 4; j++) {
        int col = n0 + wn + j * 8 + tg * 2;
        float b0 = linb[col], b1 = linb[col + 1];
        float vs0 = 0, vs1 = 0, vq0 = 0, vq1 = 0;
#pragma unroll
        for (int i = 0; i < 2; i++) {
            int row = m0 + wm + i * 16 + g;
            float v0 = acc[i][j][0] + b0, v1 = acc[i][j][1] + b1;
            float v2 = acc[i][j][2] + b0, v3 = acc[i][j][3] + b1;
            *(float2*)&g_msg2[row * F_ + col] = make_float2(v0, v1);
            *(float2*)&g_msg2[(row + 8) * F_ + col] = make_float2(v2, v3);
            vs0 += v0 + v2; vs1 += v1 + v3;
            vq0 += v0 * v0 + v2 * v2; vq1 += v1 * v1 + v3 * v3;
        }
        s0[j] = vs0; s1[j] = vs1; q0[j] = vq0; q1[j] = vq1;
    }
#pragma unroll
    for (int o = 4; o < 32; o <<= 1) {
#pragma unroll
        for (int j = 0; j < 4; j++) {
            s0[j] += __shfl_xor_sync(0xffffffffu, s0[j], o);
            s1[j] += __shfl_xor_sync(0xffffffffu, s1[j], o);
            q0[j] += __shfl_xor_sync(0xffffffffu, q0[j], o);
            q1[j] += __shfl_xor_sync(0xffffffffu, q1[j], o);
        }
    }
    if (g == 0) {
#pragma unroll
        for (int j = 0; j < 4; j++) {
            int col = n0 + wn + j * 8 + tg * 2;
            atomicAdd(&g_sum[col], s0[j]);
            atomicAdd(&g_sum[col + 1], s1[j]);
            atomicAdd(&g_sum2[col], q0[j]);
            atomicAdd(&g_sum2[col + 1], q1[j]);
        }
    }
}

// ---------------- batchnorm stats finalize ----------------
__global__ void bn_pass2() {
    int c = threadIdx.x;
    float mu = g_sum[c] * (1.0f / BN_);
    float var = g_sum2[c] * (1.0f / BN_) - mu * mu;
    g_mu[c] = mu;
    g_rstd[c] = rsqrtf(var + 1e-5f);
}

// ---------------- residual apply (+zero accumulators for next layer) ----------------
__global__ void bn_apply(const float* __restrict__ bw, const float* __restrict__ bb) {
    int n = blockIdx.x;
    int c = threadIdx.x;
    int idx = n * F_ + c;
    g_x[idx] += bw[c] * (g_msg2[idx] - g_mu[c]) * g_rstd[c] + bb[c];
    if (blockIdx.x < 18) {
        int zi = blockIdx.x * 256 + c;
        if (zi < 2048)       g_qs[zi] = 0.f;
        else if (zi < 4096)  g_ks[zi - 2048] = 0.f;
        else if (zi < 4352)  g_sum[zi - 4096] = 0.f;
        else                 g_sum2[zi - 4352] = 0.f;
    }
}

// ---------------- unpack ----------------
__global__ void unpack_kernel(float* __restrict__ out) {
    int b = blockIdx.x >> 8;
    int n = blockIdx.x & 255;
    int f = threadIdx.x;
    float v = g_x[(b * N_ + n) * F_ + f];
    if (n < N0_) out[(b * F_ + f) * N0_ + n] = v;
    else         out[B_ * F_ * N0_ + (b * F_ + f) * N1_ + (n - N0_)] = v;
}

// ---------------- host ----------------
extern "C" void kernel_launch(void* const* d_in, const int* in_sizes, int n_in,
                              void* d_out, int out_size) {
    const float* desc0  = (const float*)d_in[0];
    const float* desc1  = (const float*)d_in[1];
    const float* conv_w = (const float*)d_in[2];
    const float* conv_q = (const float*)d_in[3];
    const float* conv_k = (const float*)d_in[4];
    const float* conv_b = (const float*)d_in[5];
    const float* lin_w  = (const float*)d_in[6];
    const float* lin_b  = (const float*)d_in[7];
    const float* bn_w   = (const float*)d_in[8];
    const float* bn_b   = (const float*)d_in[9];
    float* out = (float*)d_out;

    pack_kernel<<<BN_, F_>>>(desc0, desc1);

    for (int i = 0; i < L_; i++) {
        gemm_H_mma<<<dim3(4, 16, 2), 128>>>(conv_w + (size_t)i * 2 * F_ * F_,
                                            conv_q + i * F_, conv_k + i * F_);
        alpha_kernel<<<128, 256>>>();
        attn_gemm_mma<<<dim3(4, 2, 8), 128>>>(conv_b + i * F_);
        transpose_lw<<<dim3(16, 8), dim3(32, 8)>>>(lin_w + (size_t)i * F_ * 2 * F_);
        lin_gemm_mma<<<dim3(4, 16), 128>>>(lin_b + i * F_);
        bn_pass2<<<1, F_>>>();
        bn_apply<<<BN_, F_>>>(bn_w + i * F_, bn_b + i * F_);
    }

    unpack_kernel<<<BN_, F_>>>(out);
}

// round 10
// speedup vs baseline: 1.0039x; 1.0039x over previous
#include <cuda_runtime.h>
#include <math.h>

// ---------------- problem constants ----------------
#define B_   4
#define F_   256
#define N0_  128
#define N1_  128
#define N_   256        // nodes per graph
#define BN_  1024       // total nodes
#define L_   3

#define ASTR 20         // smem stride for A tile (64 x 16), conflict-free + 16B aligned
#define BSTR 72         // smem stride for B tile (16 x 64), conflict-free + 16B aligned

// ---------------- scratch (device globals; no allocation) ----------------
__device__ float g_x[BN_ * F_];
__device__ float g_H[2 * BN_ * F_];
__device__ float g_qs[2 * BN_];
__device__ float g_ks[2 * BN_];
__device__ float g_alpha[B_ * N_ * N_];
__device__ float g_msg1[BN_ * F_];
__device__ float g_msg2[BN_ * F_];
__device__ float g_lwT[2 * F_ * F_];
__device__ float g_sum[F_];
__device__ float g_sum2[F_];
__device__ float g_mu[F_];
__device__ float g_rstd[F_];

// ---------------- tf32 helpers ----------------
__device__ __forceinline__ unsigned f2tf(float f) {
    unsigned u;
    asm("cvt.rna.tf32.f32 %0, %1;" : "=r"(u) : "f"(f));
    return u;
}

__device__ __forceinline__ void mma8(float* d, const unsigned* a, const unsigned* b) {
    asm volatile(
        "mma.sync.aligned.m16n8k8.row.col.f32.tf32.tf32.f32 "
        "{%0,%1,%2,%3},{%4,%5,%6,%7},{%8,%9},{%0,%1,%2,%3};\n"
        : "+f"(d[0]), "+f"(d[1]), "+f"(d[2]), "+f"(d[3])
        : "r"(a[0]), "r"(a[1]), "r"(a[2]), "r"(a[3]), "r"(b[0]), "r"(b[1]));
}

// 64x64 block tile, 4 warps (warp tile 32x32 = 2 m-frags x 4 n-frags), BK=16
__device__ __forceinline__ void compute_bk(const unsigned* As, const unsigned* Bs,
                                           float acc[2][4][4], int lane, int wm, int wn) {
    int g = lane >> 2, tg = lane & 3;
#pragma unroll
    for (int s = 0; s < 2; s++) {
        int kb = s * 8;
        unsigned a[2][4], b[4][2];
#pragma unroll
        for (int i = 0; i < 2; i++) {
            int r0 = wm + i * 16 + g;
            a[i][0] = As[r0 * ASTR + kb + tg];
            a[i][1] = As[(r0 + 8) * ASTR + kb + tg];
            a[i][2] = As[r0 * ASTR + kb + tg + 4];
            a[i][3] = As[(r0 + 8) * ASTR + kb + tg + 4];
        }
#pragma unroll
        for (int j = 0; j < 4; j++) {
            b[j][0] = Bs[(kb + tg) * BSTR + wn + j * 8 + g];
            b[j][1] = Bs[(kb + tg + 4) * BSTR + wn + j * 8 + g];
        }
#pragma unroll
        for (int i = 0; i < 2; i++)
#pragma unroll
            for (int j = 0; j < 4; j++) mma8(acc[i][j], a[i], b[j]);
    }
}

__device__ __forceinline__ void store_tiles(unsigned* Asm, unsigned* Bsm,
                                            const float4* ra, const float4* rb, int t) {
#pragma unroll
    for (int u = 0; u < 2; u++) {
        int idx = t * 2 + u;
        {
            int row = idx >> 2, c4 = (idx & 3) * 4;
            uint4 w = make_uint4(f2tf(ra[u].x), f2tf(ra[u].y), f2tf(ra[u].z), f2tf(ra[u].w));
            *(uint4*)&Asm[row * ASTR + c4] = w;
        }
        {
            int row = idx >> 4, c4 = (idx & 15) * 4;
            uint4 w = make_uint4(f2tf(rb[u].x), f2tf(rb[u].y), f2tf(rb[u].z), f2tf(rb[u].w));
            *(uint4*)&Bsm[row * BSTR + c4] = w;
        }
    }
}

// ---------------- pack (+zero accumulators for layer 0) ----------------
__global__ void pack_kernel(const float* __restrict__ d0, const float* __restrict__ d1) {
    int b = blockIdx.x >> 8;
    int n = blockIdx.x & 255;
    int f = threadIdx.x;
    float v;
    if (n < N0_) v = d0[(b * F_ + f) * N0_ + n];
    else         v = d1[(b * F_ + f) * N1_ + (n - N0_)];
    g_x[(b * N_ + n) * F_ + f] = v;
    if (blockIdx.x < 18) {
        int zi = blockIdx.x * 256 + f;
        if (zi < 2048)       g_qs[zi] = 0.f;
        else if (zi < 4096)  g_ks[zi - 2048] = 0.f;
        else if (zi < 4352)  g_sum[zi - 4096] = 0.f;
        else                 g_sum2[zi - 4352] = 0.f;
    }
}

// ---------------- H = x @ W[r], fused q/k scores. grid (4,16,2) x 128 ----------------
__global__ __launch_bounds__(128) void gemm_H_mma(const float* __restrict__ W,
                                                  const float* __restrict__ q,
                                                  const float* __restrict__ kvec) {
    int r = blockIdx.z;
    const float* Bp = W + r * F_ * F_;
    float* C = g_H + (size_t)r * BN_ * F_;
    int m0 = blockIdx.y * 64, n0 = blockIdx.x * 64;
    __shared__ unsigned Asm[64 * ASTR], Bsm[16 * BSTR];
    int t = threadIdx.x, lane = t & 31, warp = t >> 5;
    int wm = (warp >> 1) * 32, wn = (warp & 1) * 32;
    float acc[2][4][4] = {};
    float4 ra[2], rb[2];
#pragma unroll
    for (int u = 0; u < 2; u++) {
        int idx = t * 2 + u;
        { int row = idx >> 2, c4 = (idx & 3) * 4; ra[u] = *(const float4*)&g_x[(m0 + row) * F_ + c4]; }
        { int row = idx >> 4, c4 = (idx & 15) * 4; rb[u] = *(const float4*)&Bp[row * F_ + n0 + c4]; }
    }
    for (int k0 = 0; k0 < F_; k0 += 16) {
        store_tiles(Asm, Bsm, ra, rb, t);
        __syncthreads();
        int kn = k0 + 16;
        if (kn < F_) {
#pragma unroll
            for (int u = 0; u < 2; u++) {
                int idx = t * 2 + u;
                { int row = idx >> 2, c4 = (idx & 3) * 4; ra[u] = *(const float4*)&g_x[(m0 + row) * F_ + kn + c4]; }
                { int row = idx >> 4, c4 = (idx & 15) * 4; rb[u] = *(const float4*)&Bp[(kn + row) * F_ + n0 + c4]; }
            }
        }
        compute_bk(Asm, Bsm, acc, lane, wm, wn);
        __syncthreads();
    }
    int g = lane >> 2, tg = lane & 3;
#pragma unroll
    for (int i = 0; i < 2; i++)
#pragma unroll
        for (int j = 0; j < 4; j++) {
            int row = m0 + wm + i * 16 + g, col = n0 + wn + j * 8 + tg * 2;
            *(float2*)&C[row * F_ + col] = make_float2(acc[i][j][0], acc[i][j][1]);
            *(float2*)&C[(row + 8) * F_ + col] = make_float2(acc[i][j][2], acc[i][j][3]);
        }
    // fused per-node q/k scores (partial over this block's 64 cols)
    float2 qv[4], kv[4];
#pragma unroll
    for (int j = 0; j < 4; j++) {
        int col = n0 + wn + j * 8 + tg * 2;
        qv[j] = *(const float2*)&q[col];
        kv[j] = *(const float2*)&kvec[col];
    }
#pragma unroll
    for (int i = 0; i < 2; i++) {
        float qp0 = 0, qp1 = 0, kp0 = 0, kp1 = 0;
#pragma unroll
        for (int j = 0; j < 4; j++) {
            qp0 += acc[i][j][0] * qv[j].x + acc[i][j][1] * qv[j].y;
            qp1 += acc[i][j][2] * qv[j].x + acc[i][j][3] * qv[j].y;
            kp0 += acc[i][j][0] * kv[j].x + acc[i][j][1] * kv[j].y;
            kp1 += acc[i][j][2] * kv[j].x + acc[i][j][3] * kv[j].y;
        }
#pragma unroll
        for (int o = 1; o < 4; o <<= 1) {
            qp0 += __shfl_xor_sync(0xffffffffu, qp0, o);
            qp1 += __shfl_xor_sync(0xffffffffu, qp1, o);
            kp0 += __shfl_xor_sync(0xffffffffu, kp0, o);
            kp1 += __shfl_xor_sync(0xffffffffu, kp1, o);
        }
        if (tg == 0) {
            int row = m0 + wm + i * 16 + g;
            atomicAdd(&g_qs[r * BN_ + row], qp0);
            atomicAdd(&g_qs[r * BN_ + row + 8], qp1);
            atomicAdd(&g_ks[r * BN_ + row], kp0);
            atomicAdd(&g_ks[r * BN_ + row + 8], kp1);
        }
    }
}

// ---------------- attention weights: one warp per dst node ----------------
__global__ void alpha_kernel() {
    int warp = (blockIdx.x * blockDim.x + threadIdx.x) >> 5;
    int lane = threadIdx.x & 31;
    int g = warp >> 8;
    int d = warp & 255;
    int dc = d >> 7;
    int nd = g * N_ + d;
    float qs0 = g_qs[nd];
    float qs1 = g_qs[BN_ + nd];
    float l[8];
    float mx = -INFINITY;
#pragma unroll
    for (int j = 0; j < 8; j++) {
        int s = j * 32 + lane;
        int r = (s >> 7) ^ dc;
        float ks = g_ks[r * BN_ + g * N_ + s];
        float qv = r ? qs1 : qs0;
        float v = qv + ks;
        v = v >= 0.0f ? v : 0.2f * v;
        if (s == d) v = -INFINITY;
        l[j] = v;
        mx = fmaxf(mx, v);
    }
#pragma unroll
    for (int o = 16; o; o >>= 1) mx = fmaxf(mx, __shfl_xor_sync(0xffffffffu, mx, o));
    float sum = 0.0f;
#pragma unroll
    for (int j = 0; j < 8; j++) { l[j] = expf(l[j] - mx); sum += l[j]; }
#pragma unroll
    for (int o = 16; o; o >>= 1) sum += __shfl_xor_sync(0xffffffffu, sum, o);
    float inv = 1.0f / (sum + 1e-16f);
#pragma unroll
    for (int j = 0; j < 8; j++) g_alpha[nd * N_ + j * 32 + lane] = l[j] * inv;
}

// ---------------- attention aggregation GEMM, relu(+conv_b). grid (4,2,8) x 128 ----------------
__global__ __launch_bounds__(128) void attn_gemm_mma(const float* __restrict__ convb) {
    int z = blockIdx.z;
    int gg = z >> 1, dc = z & 1;
    int m0 = blockIdx.y * 64, n0 = blockIdx.x * 64;
    const float* A = g_alpha + (size_t)(gg * N_ + dc * 128) * N_;
    float* C = g_msg1 + (size_t)(gg * N_ + dc * 128) * F_;
    __shared__ unsigned Asm[64 * ASTR], Bsm[16 * BSTR];
    int t = threadIdx.x, lane = t & 31, warp = t >> 5;
    int wm = (warp >> 1) * 32, wn = (warp & 1) * 32;
    float acc[2][4][4] = {};
    float4 ra[2], rb[2];
    auto loadg = [&](int k0) {
#pragma unroll
        for (int u = 0; u < 2; u++) {
            int idx = t * 2 + u;
            { int row = idx >> 2, c4 = (idx & 3) * 4; ra[u] = *(const float4*)&A[(m0 + row) * N_ + k0 + c4]; }
            {
                int row = idx >> 4, c4 = (idx & 15) * 4;
                int s = k0 + row;
                int rel = (s >> 7) ^ dc;
                rb[u] = *(const float4*)&g_H[((size_t)rel * BN_ + gg * N_ + s) * F_ + n0 + c4];
            }
        }
    };
    loadg(0);
    for (int k0 = 0; k0 < N_; k0 += 16) {
        store_tiles(Asm, Bsm, ra, rb, t);
        __syncthreads();
        if (k0 + 16 < N_) loadg(k0 + 16);
        compute_bk(Asm, Bsm, acc, lane, wm, wn);
        __syncthreads();
    }
    int g = lane >> 2, tg = lane & 3;
#pragma unroll
    for (int i = 0; i < 2; i++)
#pragma unroll
        for (int j = 0; j < 4; j++) {
            int row = m0 + wm + i * 16 + g, col = n0 + wn + j * 8 + tg * 2;
            float b0 = convb[col], b1 = convb[col + 1];
            float v0 = fmaxf(acc[i][j][0] + b0, 0.f), v1 = fmaxf(acc[i][j][1] + b1, 0.f);
            float v2 = fmaxf(acc[i][j][2] + b0, 0.f), v3 = fmaxf(acc[i][j][3] + b1, 0.f);
            *(float2*)&C[row * F_ + col] = make_float2(v0, v1);
            *(float2*)&C[(row + 8) * F_ + col] = make_float2(v2, v3);
        }
}

// ---------------- transpose lin_w [256 o][512 k] -> g_lwT [512 k][256 o] ----------------
__global__ void transpose_lw(const float* __restrict__ lw) {
    __shared__ float tt[32][33];
    int k0 = blockIdx.x * 32, o0 = blockIdx.y * 32;
    int tx = threadIdx.x, ty = threadIdx.y;
    for (int i = ty; i < 32; i += 8) tt[i][tx] = lw[(o0 + i) * (2 * F_) + k0 + tx];
    __syncthreads();
    for (int i = ty; i < 32; i += 8) g_lwT[(k0 + i) * F_ + o0 + tx] = tt[tx][i];
}

// ---------------- msg2 = [x, msg1] @ lwT + lin_b, fused BN partial sums. grid (4,16) x 128 ----------------
__global__ __launch_bounds__(128) void lin_gemm_mma(const float* __restrict__ linb) {
    int m0 = blockIdx.y * 64, n0 = blockIdx.x * 64;
    __shared__ unsigned Asm[64 * ASTR], Bsm[16 * BSTR];
    int t = threadIdx.x, lane = t & 31, warp = t >> 5;
    int wm = (warp >> 1) * 32, wn = (warp & 1) * 32;
    float acc[2][4][4] = {};
    float4 ra[2], rb[2];
    auto loadg = [&](int k0) {
        const float* Abase = (k0 < F_) ? g_x : g_msg1;
        int kk = (k0 < F_) ? k0 : k0 - F_;
#pragma unroll
        for (int u = 0; u < 2; u++) {
            int idx = t * 2 + u;
            { int row = idx >> 2, c4 = (idx & 3) * 4; ra[u] = *(const float4*)&Abase[(m0 + row) * F_ + kk + c4]; }
            { int row = idx >> 4, c4 = (idx & 15) * 4; rb[u] = *(const float4*)&g_lwT[(k0 + row) * F_ + n0 + c4]; }
        }
    };
    loadg(0);
    for (int k0 = 0; k0 < 2 * F_; k0 += 16) {
        store_tiles(Asm, Bsm, ra, rb, t);
        __syncthreads();
        if (k0 + 16 < 2 * F_) loadg(k0 + 16);
        compute_bk(Asm, Bsm, acc, lane, wm, wn);
        __syncthreads();
    }
    int g = lane >> 2, tg = lane & 3;
    float s0[4], s1[4], q0[4], q1[4];
#pragma unroll
    for (int j = 0; j < 4; j++) {
        int col = n0 + wn + j * 8 + tg * 2;
        float b0 = linb[col], b1 = linb[col + 1];
        float vs0 = 0, vs1 = 0, vq0 = 0, vq1 = 0;
#pragma unroll
        for (int i = 0; i < 2; i++) {
            int row = m0 + wm + i * 16 + g;
            float v0 = acc[i][j][0] + b0, v1 = acc[i][j][1] + b1;
            float v2 = acc[i][j][2] + b0, v3 = acc[i][j][3] + b1;
            *(float2*)&g_msg2[row * F_ + col] = make_float2(v0, v1);
            *(float2*)&g_msg2[(row + 8) * F_ + col] = make_float2(v2, v3);
            vs0 += v0 + v2; vs1 += v1 + v3;
            vq0 += v0 * v0 + v2 * v2; vq1 += v1 * v1 + v3 * v3;
        }
        s0[j] = vs0; s1[j] = vs1; q0[j] = vq0; q1[j] = vq1;
    }
#pragma unroll
    for (int o = 4; o < 32; o <<= 1) {
#pragma unroll
        for (int j = 0; j < 4; j++) {
            s0[j] += __shfl_xor_sync(0xffffffffu, s0[j], o);
            s1[j] += __shfl_xor_sync(0xffffffffu, s1[j], o);
            q0[j] += __shfl_xor_sync(0xffffffffu, q0[j], o);
            q1[j] += __shfl_xor_sync(0xffffffffu, q1[j], o);
        }
    }
    if (g == 0) {
#pragma unroll
        for (int j = 0; j < 4; j++) {
            int col = n0 + wn + j * 8 + tg * 2;
            atomicAdd(&g_sum[col], s0[j]);
            atomicAdd(&g_sum[col + 1], s1[j]);
            atomicAdd(&g_sum2[col], q0[j]);
            atomicAdd(&g_sum2[col + 1], q1[j]);
        }
    }
}

// ---------------- batchnorm stats finalize ----------------
__global__ void bn_pass2() {
    int c = threadIdx.x;
    float mu = g_sum[c] * (1.0f / BN_);
    float var = g_sum2[c] * (1.0f / BN_) - mu * mu;
    g_mu[c] = mu;
    g_rstd[c] = rsqrtf(var + 1e-5f);
}

// ---------------- residual apply (+zero accumulators for next layer) ----------------
__global__ void bn_apply(const float* __restrict__ bw, const float* __restrict__ bb) {
    int n = blockIdx.x;
    int c = threadIdx.x;
    int idx = n * F_ + c;
    g_x[idx] += bw[c] * (g_msg2[idx] - g_mu[c]) * g_rstd[c] + bb[c];
    if (blockIdx.x < 18) {
        int zi = blockIdx.x * 256 + c;
        if (zi < 2048)       g_qs[zi] = 0.f;
        else if (zi < 4096)  g_ks[zi - 2048] = 0.f;
        else if (zi < 4352)  g_sum[zi - 4096] = 0.f;
        else                 g_sum2[zi - 4352] = 0.f;
    }
}

// ---------------- unpack ----------------
__global__ void unpack_kernel(float* __restrict__ out) {
    int b = blockIdx.x >> 8;
    int n = blockIdx.x & 255;
    int f = threadIdx.x;
    float v = g_x[(b * N_ + n) * F_ + f];
    if (n < N0_) out[(b * F_ + f) * N0_ + n] = v;
    else         out[B_ * F_ * N0_ + (b * F_ + f) * N1_ + (n - N0_)] = v;
}

// ---------------- host ----------------
extern "C" void kernel_launch(void* const* d_in, const int* in_sizes, int n_in,
                              void* d_out, int out_size) {
    const float* desc0  = (const float*)d_in[0];
    const float* desc1  = (const float*)d_in[1];
    const float* conv_w = (const float*)d_in[2];
    const float* conv_q = (const float*)d_in[3];
    const float* conv_k = (const float*)d_in[4];
    const float* conv_b = (const float*)d_in[5];
    const float* lin_w  = (const float*)d_in[6];
    const float* lin_b  = (const float*)d_in[7];
    const float* bn_w   = (const float*)d_in[8];
    const float* bn_b   = (const float*)d_in[9];
    float* out = (float*)d_out;

    pack_kernel<<<BN_, F_>>>(desc0, desc1);

    for (int i = 0; i < L_; i++) {
        gemm_H_mma<<<dim3(4, 16, 2), 128>>>(conv_w + (size_t)i * 2 * F_ * F_,
                                            conv_q + i * F_, conv_k + i * F_);
        alpha_kernel<<<128, 256>>>();
        attn_gemm_mma<<<dim3(4, 2, 8), 128>>>(conv_b + i * F_);
        transpose_lw<<<dim3(16, 8), dim3(32, 8)>>>(lin_w + (size_t)i * F_ * 2 * F_);
        lin_gemm_mma<<<dim3(4, 16), 128>>>(lin_b + i * F_);
        bn_pass2<<<1, F_>>>();
        bn_apply<<<BN_, F_>>>(bn_w + i * F_, bn_b + i * F_);
    }

    unpack_kernel<<<BN_, F_>>>(out);
}

// round 11
// speedup vs baseline: 1.7854x; 1.7784x over previous
#include <cuda_runtime.h>
#include <math.h>

// ---------------- problem constants ----------------
#define B_   4
#define F_   256
#define N0_  128
#define N1_  128
#define N_   256
#define BN_  1024
#define L_   3

#define ASH 36    // smem word-stride, 32-wide A tiles (16B aligned, conflict-free)
#define BSH 72    // smem word-stride, 64-wide B tiles
#define ALS 264   // smem word-stride, 256-wide alpha tile

// ---------------- scratch ----------------
__device__ float g_x[BN_ * F_];            // exact features
__device__ float g_xt[BN_ * F_];           // tf32-rounded features
__device__ float g_Ht[2 * BN_ * F_];       // rounded relation transforms
__device__ float g_Wt[L_ * 2 * F_ * F_];   // rounded conv weights
__device__ float g_lwT[L_ * 2 * F_ * F_];  // rounded transposed lin weights
__device__ float g_msg1t[BN_ * F_];        // rounded relu output
__device__ float g_msg2[BN_ * F_];         // exact lin output
__device__ float g_qs[2 * BN_];
__device__ float g_ks[2 * BN_];
__device__ float g_sum[F_], g_sum2[F_], g_mu[F_], g_rstd[F_];

// ---------------- helpers ----------------
__device__ __forceinline__ unsigned f2tf(float f) {
    unsigned u;
    asm("cvt.rna.tf32.f32 %0, %1;" : "=r"(u) : "f"(f));
    return u;
}
__device__ __forceinline__ float rndf(float f) { return __uint_as_float(f2tf(f)); }

__device__ __forceinline__ void mma8(float* d, const unsigned* a, const unsigned* b) {
    asm volatile(
        "mma.sync.aligned.m16n8k8.row.col.f32.tf32.tf32.f32 "
        "{%0,%1,%2,%3},{%4,%5,%6,%7},{%8,%9},{%0,%1,%2,%3};\n"
        : "+f"(d[0]), "+f"(d[1]), "+f"(d[2]), "+f"(d[3])
        : "r"(a[0]), "r"(a[1]), "r"(a[2]), "r"(a[3]), "r"(b[0]), "r"(b[1]));
}

__device__ __forceinline__ void cpa16(float* smem, const float* gmem) {
    unsigned s = (unsigned)__cvta_generic_to_shared(smem);
    asm volatile("cp.async.cg.shared.global [%0], [%1], 16;\n" :: "r"(s), "l"(gmem));
}
#define CP_COMMIT() asm volatile("cp.async.commit_group;\n")
#define CP_WAIT1()  asm volatile("cp.async.wait_group 1;\n")
#define CP_WAIT0()  asm volatile("cp.async.wait_group 0;\n")

// ---------------- prep: pack + zero, round conv_w, transpose+round lin_w ----------------
__global__ void pack_kernel(const float* __restrict__ d0, const float* __restrict__ d1) {
    int b = blockIdx.x >> 8;
    int n = blockIdx.x & 255;
    int f = threadIdx.x;
    float v;
    if (n < N0_) v = d0[(b * F_ + f) * N0_ + n];
    else         v = d1[(b * F_ + f) * N1_ + (n - N0_)];
    int idx = (b * N_ + n) * F_ + f;
    g_x[idx] = v;
    g_xt[idx] = rndf(v);
    if (blockIdx.x < 18) {
        int zi = blockIdx.x * 256 + f;
        if (zi < 2048)       g_qs[zi] = 0.f;
        else if (zi < 4096)  g_ks[zi - 2048] = 0.f;
        else if (zi < 4352)  g_sum[zi - 4096] = 0.f;
        else                 g_sum2[zi - 4352] = 0.f;
    }
}

__global__ void round_convw(const float* __restrict__ cw) {
    int i = blockIdx.x * 256 + threadIdx.x;
    g_Wt[i] = rndf(cw[i]);
}

__global__ void transpose_lw_all(const float* __restrict__ lw) {
    __shared__ float tt[32][33];
    int l = blockIdx.z;
    int k0 = blockIdx.x * 32, o0 = blockIdx.y * 32;
    const float* L = lw + (size_t)l * F_ * 2 * F_;
    float* T = g_lwT + (size_t)l * 2 * F_ * F_;
    int tx = threadIdx.x, ty = threadIdx.y;
    for (int i = ty; i < 32; i += 8) tt[i][tx] = L[(o0 + i) * (2 * F_) + k0 + tx];
    __syncthreads();
    for (int i = ty; i < 32; i += 8) T[(k0 + i) * F_ + o0 + tx] = rndf(tt[tx][i]);
}

// ---------------- gemm_H: H[r]=x@W[r] (rounded out) + fused q/k scores ----------------
// grid (4,16,2) x 256, block tile 64x64, warp tile 16x32, BK=32 double-buffered
__global__ __launch_bounds__(256) void gemm_H_mma(int layer, const float* __restrict__ q,
                                                  const float* __restrict__ kvec) {
    int r = blockIdx.z;
    const float* Bp = g_Wt + ((size_t)layer * 2 + r) * F_ * F_;
    float* C = g_Ht + (size_t)r * BN_ * F_;
    int m0 = blockIdx.y * 64, n0 = blockIdx.x * 64;
    __shared__ float Asm[2][64 * ASH];
    __shared__ float Bsm[2][32 * BSH];
    int t = threadIdx.x, lane = t & 31, warp = t >> 5;
    int wm = (warp >> 1) * 16, wn = (warp & 1) * 32;
    int g = lane >> 2, tg = lane & 3;

    auto loadst = [&](int st, int k0) {
#pragma unroll
        for (int u = 0; u < 2; u++) {
            int idx = t + u * 256;
            { int row = idx >> 3, seg = idx & 7;
              cpa16(&Asm[st][row * ASH + seg * 4], &g_xt[(m0 + row) * F_ + k0 + seg * 4]); }
            { int row = idx >> 4, seg = idx & 15;
              cpa16(&Bsm[st][row * BSH + seg * 4], &Bp[(k0 + row) * F_ + n0 + seg * 4]); }
        }
        CP_COMMIT();
    };

    float acc[4][4] = {};
    loadst(0, 0);
    for (int i = 0; i < 8; i++) {
        if (i < 7) { loadst((i + 1) & 1, (i + 1) * 32); CP_WAIT1(); } else CP_WAIT0();
        __syncthreads();
        const float* As = Asm[i & 1];
        const float* Bs = Bsm[i & 1];
#pragma unroll
        for (int ks = 0; ks < 4; ks++) {
            int kb = ks * 8;
            unsigned a[4];
            a[0] = __float_as_uint(As[(wm + g) * ASH + kb + tg]);
            a[1] = __float_as_uint(As[(wm + g + 8) * ASH + kb + tg]);
            a[2] = __float_as_uint(As[(wm + g) * ASH + kb + tg + 4]);
            a[3] = __float_as_uint(As[(wm + g + 8) * ASH + kb + tg + 4]);
#pragma unroll
            for (int j = 0; j < 4; j++) {
                unsigned b[2];
                b[0] = __float_as_uint(Bs[(kb + tg) * BSH + wn + j * 8 + g]);
                b[1] = __float_as_uint(Bs[(kb + tg + 4) * BSH + wn + j * 8 + g]);
                mma8(acc[j], a, b);
            }
        }
        __syncthreads();
    }
    int row = m0 + wm + g;
#pragma unroll
    for (int j = 0; j < 4; j++) {
        int col = n0 + wn + j * 8 + tg * 2;
        *(float2*)&C[row * F_ + col] = make_float2(rndf(acc[j][0]), rndf(acc[j][1]));
        *(float2*)&C[(row + 8) * F_ + col] = make_float2(rndf(acc[j][2]), rndf(acc[j][3]));
    }
    // fused q/k partial dots over this block's 64 columns
    float qp0 = 0, qp1 = 0, kp0 = 0, kp1 = 0;
#pragma unroll
    for (int j = 0; j < 4; j++) {
        int col = n0 + wn + j * 8 + tg * 2;
        float2 qv = *(const float2*)&q[col];
        float2 kv = *(const float2*)&kvec[col];
        qp0 += acc[j][0] * qv.x + acc[j][1] * qv.y;
        qp1 += acc[j][2] * qv.x + acc[j][3] * qv.y;
        kp0 += acc[j][0] * kv.x + acc[j][1] * kv.y;
        kp1 += acc[j][2] * kv.x + acc[j][3] * kv.y;
    }
#pragma unroll
    for (int o = 1; o < 4; o <<= 1) {
        qp0 += __shfl_xor_sync(0xffffffffu, qp0, o);
        qp1 += __shfl_xor_sync(0xffffffffu, qp1, o);
        kp0 += __shfl_xor_sync(0xffffffffu, kp0, o);
        kp1 += __shfl_xor_sync(0xffffffffu, kp1, o);
    }
    if (tg == 0) {
        atomicAdd(&g_qs[r * BN_ + row], qp0);
        atomicAdd(&g_qs[r * BN_ + row + 8], qp1);
        atomicAdd(&g_ks[r * BN_ + row], kp0);
        atomicAdd(&g_ks[r * BN_ + row + 8], kp1);
    }
}

// ---------------- attn: fused alpha softmax + aggregation GEMM + relu(+bias) ----------------
// grid (4,4,8) x 256, block tile 32x64, warp tile 16x16, alpha whole-K in smem, B BK=16 db
__global__ __launch_bounds__(256) void attn_gemm_mma(const float* __restrict__ convb) {
    int z = blockIdx.z;
    int gg = z >> 1, dc = z & 1;
    int m0c = blockIdx.y * 32;           // within 128-row (g,dc) chunk
    int n0 = blockIdx.x * 64;
    float* C = g_msg1t + (size_t)(gg * N_ + dc * 128 + m0c) * F_;
    __shared__ float Asm[32 * ALS];
    __shared__ float Bsm[2][16 * BSH];
    int t = threadIdx.x, lane = t & 31, warp = t >> 5;
    int wm = (warp >> 2) * 16, wn = (warp & 3) * 16;
    int g = lane >> 2, tg = lane & 3;

    auto loadB = [&](int st, int k0) {
        int row = t >> 4, seg = t & 15;
        int s = k0 + row;
        int rel = (s >> 7) ^ dc;
        cpa16(&Bsm[st][row * BSH + seg * 4],
              &g_Ht[((size_t)rel * BN_ + gg * N_ + s) * F_ + n0 + seg * 4]);
        CP_COMMIT();
    };
    loadB(0, 0);

    // alpha prologue: each warp computes softmax for 4 dst rows, writes tf32 to smem
#pragma unroll
    for (int rr = 0; rr < 4; rr++) {
        int rl = warp * 4 + rr;
        int d = dc * 128 + m0c + rl;
        int nd = gg * N_ + d;
        float qs0 = g_qs[nd];
        float qs1 = g_qs[BN_ + nd];
        float l[8];
        float mx = -INFINITY;
#pragma unroll
        for (int j = 0; j < 8; j++) {
            int s = j * 32 + lane;
            int rel = (s >> 7) ^ dc;
            float ksv = g_ks[rel * BN_ + gg * N_ + s];
            float qv = rel ? qs1 : qs0;
            float v = qv + ksv;
            v = v >= 0.0f ? v : 0.2f * v;
            if (s == d) v = -INFINITY;
            l[j] = v;
            mx = fmaxf(mx, v);
        }
#pragma unroll
        for (int o = 16; o; o >>= 1) mx = fmaxf(mx, __shfl_xor_sync(0xffffffffu, mx, o));
        float sum = 0.0f;
#pragma unroll
        for (int j = 0; j < 8; j++) { l[j] = expf(l[j] - mx); sum += l[j]; }
#pragma unroll
        for (int o = 16; o; o >>= 1) sum += __shfl_xor_sync(0xffffffffu, sum, o);
        float inv = 1.0f / (sum + 1e-16f);
#pragma unroll
        for (int j = 0; j < 8; j++) Asm[rl * ALS + j * 32 + lane] = rndf(l[j] * inv);
    }
    __syncthreads();

    float acc[2][4] = {};
    for (int i = 0; i < 16; i++) {
        if (i < 15) { loadB((i + 1) & 1, (i + 1) * 16); CP_WAIT1(); } else CP_WAIT0();
        __syncthreads();
        const float* Bs = Bsm[i & 1];
#pragma unroll
        for (int ks = 0; ks < 2; ks++) {
            int kb = ks * 8, kg = i * 16 + kb;
            unsigned a[4];
            a[0] = __float_as_uint(Asm[(wm + g) * ALS + kg + tg]);
            a[1] = __float_as_uint(Asm[(wm + g + 8) * ALS + kg + tg]);
            a[2] = __float_as_uint(Asm[(wm + g) * ALS + kg + tg + 4]);
            a[3] = __float_as_uint(Asm[(wm + g + 8) * ALS + kg + tg + 4]);
#pragma unroll
            for (int j = 0; j < 2; j++) {
                unsigned b[2];
                b[0] = __float_as_uint(Bs[(kb + tg) * BSH + wn + j * 8 + g]);
                b[1] = __float_as_uint(Bs[(kb + tg + 4) * BSH + wn + j * 8 + g]);
                mma8(acc[j], a, b);
            }
        }
        __syncthreads();
    }
    int row = wm + g;
#pragma unroll
    for (int j = 0; j < 2; j++) {
        int col = n0 + wn + j * 8 + tg * 2;
        float b0 = convb[col], b1 = convb[col + 1];
        *(float2*)&C[row * F_ + col] =
            make_float2(rndf(fmaxf(acc[j][0] + b0, 0.f)), rndf(fmaxf(acc[j][1] + b1, 0.f)));
        *(float2*)&C[(row + 8) * F_ + col] =
            make_float2(rndf(fmaxf(acc[j][2] + b0, 0.f)), rndf(fmaxf(acc[j][3] + b1, 0.f)));
    }
}

// ---------------- lin: msg2=[x,msg1]@lwT+b (exact out) + fused BN sums ----------------
// grid (4,32) x 256, block tile 32x64, warp tile 16x16, BK=32 double-buffered
__global__ __launch_bounds__(256) void lin_gemm_mma(int layer, const float* __restrict__ linb) {
    int m0 = blockIdx.y * 32, n0 = blockIdx.x * 64;
    const float* lwT = g_lwT + (size_t)layer * 2 * F_ * F_;
    __shared__ float Asm[2][32 * ASH];
    __shared__ float Bsm[2][32 * BSH];
    int t = threadIdx.x, lane = t & 31, warp = t >> 5;
    int wm = (warp >> 2) * 16, wn = (warp & 3) * 16;
    int g = lane >> 2, tg = lane & 3;

    auto loadst = [&](int st, int k0) {
        const float* Abase = (k0 < F_) ? g_xt : g_msg1t;
        int kk = k0 & (F_ - 1);
        { int row = t >> 3, seg = t & 7;
          cpa16(&Asm[st][row * ASH + seg * 4], &Abase[(m0 + row) * F_ + kk + seg * 4]); }
#pragma unroll
        for (int u = 0; u < 2; u++) {
            int idx = t + u * 256;
            int row = idx >> 4, seg = idx & 15;
            cpa16(&Bsm[st][row * BSH + seg * 4], &lwT[(k0 + row) * F_ + n0 + seg * 4]);
        }
        CP_COMMIT();
    };

    float acc[2][4] = {};
    loadst(0, 0);
    for (int i = 0; i < 16; i++) {
        if (i < 15) { loadst((i + 1) & 1, (i + 1) * 32); CP_WAIT1(); } else CP_WAIT0();
        __syncthreads();
        const float* As = Asm[i & 1];
        const float* Bs = Bsm[i & 1];
#pragma unroll
        for (int ks = 0; ks < 4; ks++) {
            int kb = ks * 8;
            unsigned a[4];
            a[0] = __float_as_uint(As[(wm + g) * ASH + kb + tg]);
            a[1] = __float_as_uint(As[(wm + g + 8) * ASH + kb + tg]);
            a[2] = __float_as_uint(As[(wm + g) * ASH + kb + tg + 4]);
            a[3] = __float_as_uint(As[(wm + g + 8) * ASH + kb + tg + 4]);
#pragma unroll
            for (int j = 0; j < 2; j++) {
                unsigned b[2];
                b[0] = __float_as_uint(Bs[(kb + tg) * BSH + wn + j * 8 + g]);
                b[1] = __float_as_uint(Bs[(kb + tg + 4) * BSH + wn + j * 8 + g]);
                mma8(acc[j], a, b);
            }
        }
        __syncthreads();
    }
    int row = m0 + wm + g;
#pragma unroll
    for (int j = 0; j < 2; j++) {
        int col = n0 + wn + j * 8 + tg * 2;
        float b0 = linb[col], b1 = linb[col + 1];
        float v0 = acc[j][0] + b0, v1 = acc[j][1] + b1;
        float v2 = acc[j][2] + b0, v3 = acc[j][3] + b1;
        *(float2*)&g_msg2[row * F_ + col] = make_float2(v0, v1);
        *(float2*)&g_msg2[(row + 8) * F_ + col] = make_float2(v2, v3);
        float s0 = v0 + v2, s1 = v1 + v3;
        float q0 = v0 * v0 + v2 * v2, q1 = v1 * v1 + v3 * v3;
#pragma unroll
        for (int o = 4; o < 32; o <<= 1) {
            s0 += __shfl_xor_sync(0xffffffffu, s0, o);
            s1 += __shfl_xor_sync(0xffffffffu, s1, o);
            q0 += __shfl_xor_sync(0xffffffffu, q0, o);
            q1 += __shfl_xor_sync(0xffffffffu, q1, o);
        }
        if (g == 0) {
            atomicAdd(&g_sum[col], s0);
            atomicAdd(&g_sum[col + 1], s1);
            atomicAdd(&g_sum2[col], q0);
            atomicAdd(&g_sum2[col + 1], q1);
        }
    }
}

// ---------------- BN stats finalize + zero next-layer accumulators ----------------
__global__ void bn_pass2() {
    int c = threadIdx.x;
    float mu = g_sum[c] * (1.0f / BN_);
    float var = g_sum2[c] * (1.0f / BN_) - mu * mu;
    g_mu[c] = mu;
    g_rstd[c] = rsqrtf(var + 1e-5f);
    g_sum[c] = 0.f;
    g_sum2[c] = 0.f;
    for (int i = c; i < 2 * BN_; i += 256) { g_qs[i] = 0.f; g_ks[i] = 0.f; }
}

// ---------------- residual apply (exact + rounded) ----------------
__global__ void bn_apply(const float* __restrict__ bw, const float* __restrict__ bb) {
    int c = threadIdx.x;
    int idx = blockIdx.x * F_ + c;
    float v = g_x[idx] + bw[c] * (g_msg2[idx] - g_mu[c]) * g_rstd[c] + bb[c];
    g_x[idx] = v;
    g_xt[idx] = rndf(v);
}

// ---------------- unpack ----------------
__global__ void unpack_kernel(float* __restrict__ out) {
    int b = blockIdx.x >> 8;
    int n = blockIdx.x & 255;
    int f = threadIdx.x;
    float v = g_x[(b * N_ + n) * F_ + f];
    if (n < N0_) out[(b * F_ + f) * N0_ + n] = v;
    else         out[B_ * F_ * N0_ + (b * F_ + f) * N1_ + (n - N0_)] = v;
}

// ---------------- host ----------------
extern "C" void kernel_launch(void* const* d_in, const int* in_sizes, int n_in,
                              void* d_out, int out_size) {
    const float* desc0  = (const float*)d_in[0];
    const float* desc1  = (const float*)d_in[1];
    const float* conv_w = (const float*)d_in[2];
    const float* conv_q = (const float*)d_in[3];
    const float* conv_k = (const float*)d_in[4];
    const float* conv_b = (const float*)d_in[5];
    const float* lin_w  = (const float*)d_in[6];
    const float* lin_b  = (const float*)d_in[7];
    const float* bn_w   = (const float*)d_in[8];
    const float* bn_b   = (const float*)d_in[9];
    float* out = (float*)d_out;

    pack_kernel<<<BN_, F_>>>(desc0, desc1);
    round_convw<<<L_ * 2 * F_ * F_ / 256, 256>>>(conv_w);
    transpose_lw_all<<<dim3(16, 8, L_), dim3(32, 8)>>>(lin_w);

    for (int i = 0; i < L_; i++) {
        gemm_H_mma<<<dim3(4, 16, 2), 256>>>(i, conv_q + i * F_, conv_k + i * F_);
        attn_gemm_mma<<<dim3(4, 4, 8), 256>>>(conv_b + i * F_);
        lin_gemm_mma<<<dim3(4, 32), 256>>>(i, lin_b + i * F_);
        bn_pass2<<<1, F_>>>();
        bn_apply<<<BN_, F_>>>(bn_w + i * F_, bn_b + i * F_);
    }

    unpack_kernel<<<BN_, F_>>>(out);
}

// round 12
// speedup vs baseline: 2.2679x; 1.2703x over previous
#include <cuda_runtime.h>
#include <cuda_fp16.h>
#include <math.h>

// ---------------- problem constants ----------------
#define B_   4
#define F_   256
#define N0_  128
#define N_   256
#define BN_  1024
#define L_   3

#define KW  20     // 32-bit words per 32-half smem row (16 data + 4 pad) -> conflict-free
#define ALW 132    // 32-bit words per 256-half alpha row (264 halves)

// ---------------- scratch ----------------
__device__ float  g_x[BN_ * F_];          // exact features
__device__ __half g_xh[BN_ * F_];         // half features
__device__ __half g_Hh[2 * F_ * BN_];     // H transposed: [r][e][node]
__device__ __half g_Wh[L_ * 2 * F_ * F_]; // conv W transposed: [l][r][e][f]
__device__ __half g_lwh[L_ * F_ * 2 * F_];// lin W: [l][o][k] (natural layout)
__device__ __half g_m1h[BN_ * F_];        // msg1 half [node][feat]
__device__ float  g_msg2[BN_ * F_];
__device__ float  g_qs[2 * BN_], g_ks[2 * BN_];
__device__ float  g_sum[F_], g_sum2[F_];

// ---------------- helpers ----------------
__device__ __forceinline__ void mma16(float* d, const unsigned* a, const unsigned* b) {
    asm volatile(
        "mma.sync.aligned.m16n8k16.row.col.f32.f16.f16.f32 "
        "{%0,%1,%2,%3},{%4,%5,%6,%7},{%8,%9},{%0,%1,%2,%3};\n"
        : "+f"(d[0]), "+f"(d[1]), "+f"(d[2]), "+f"(d[3])
        : "r"(a[0]), "r"(a[1]), "r"(a[2]), "r"(a[3]), "r"(b[0]), "r"(b[1]));
}

__device__ __forceinline__ void cpa16h(__half* s, const __half* g) {
    unsigned ss = (unsigned)__cvta_generic_to_shared(s);
    asm volatile("cp.async.cg.shared.global [%0], [%1], 16;\n" :: "r"(ss), "l"(g));
}
#define CP_COMMIT() asm volatile("cp.async.commit_group;\n")
#define CP_WAIT1()  asm volatile("cp.async.wait_group 1;\n")

// ---------------- prep: pack + zero + round/transpose weights ----------------
__global__ void prep_kernel(const float* __restrict__ d0, const float* __restrict__ d1,
                            const float* __restrict__ cw, const float* __restrict__ lw) {
    __shared__ float s[32][33];
    int bid = blockIdx.x, t = threadIdx.x;
    if (bid < 1024) {
        int b = bid >> 8, n = bid & 255;
        float v = (n < N0_) ? d0[(b * F_ + t) * N0_ + n]
                            : d1[(b * F_ + t) * N0_ + (n - N0_)];
        int idx = (b * N_ + n) * F_ + t;
        g_x[idx] = v;
        g_xh[idx] = __float2half_rn(v);
        if (bid < 18) {
            int zi = bid * 256 + t;
            if (zi < 2048)       g_qs[zi] = 0.f;
            else if (zi < 4096)  g_ks[zi - 2048] = 0.f;
            else if (zi < 4352)  g_sum[zi - 4096] = 0.f;
            else                 g_sum2[zi - 4352] = 0.f;
        }
    } else if (bid < 1408) {
        int tt = bid - 1024, mat = tt >> 6, tile = tt & 63;
        int fr = (tile >> 3) * 32, ec = (tile & 7) * 32;
        int tx = t & 31, ty = t >> 5;
        for (int i = ty; i < 32; i += 8) s[i][tx] = cw[(mat * F_ + fr + i) * F_ + ec + tx];
        __syncthreads();
        for (int i = ty; i < 32; i += 8)
            g_Wh[((size_t)mat * F_ + ec + i) * F_ + fr + tx] = __float2half_rn(s[tx][i]);
    } else {
        size_t i0 = (size_t)(bid - 1408) * 512 + t;
        g_lwh[i0] = __float2half_rn(lw[i0]);
        g_lwh[i0 + 256] = __float2half_rn(lw[i0 + 256]);
    }
}

// ---------------- gemm_H: H[r]^T = (x@W[r])^T + fused q/k scores ----------------
// grid (4,16,2) x 128, block 64x64, warp 32x32, BK=32, 3-stage cp.async
__global__ __launch_bounds__(128) void gemm_H_k(int layer, const float* __restrict__ q,
                                                const float* __restrict__ kvec) {
    int r = blockIdx.z;
    int m0 = blockIdx.y * 64, n0 = blockIdx.x * 64;
    __shared__ __align__(16) unsigned char RAW[3 * 10240];
    int t = threadIdx.x, lane = t & 31, warp = t >> 5;
    int wm = (warp >> 1) * 32, wn = (warp & 1) * 32;
    int g = lane >> 2, tg = lane & 3;
    const __half* Wp = g_Wh + (size_t)(layer * 2 + r) * F_ * F_;

    if (blockIdx.x == 0 && blockIdx.y == 0 && blockIdx.z == 0) {
        for (int i = t; i < F_; i += 128) { g_sum[i] = 0.f; g_sum2[i] = 0.f; }
    }

    auto stA = [&](int s) { return (__half*)(RAW + s * 10240); };
    auto stB = [&](int s) { return (__half*)(RAW + s * 10240 + 5120); };
    auto loadst = [&](int s, int k0) {
        __half* A = stA(s); __half* Bm = stB(s);
#pragma unroll
        for (int u = 0; u < 2; u++) {
            int idx = t + u * 128;
            int row = idx >> 2, seg = idx & 3;
            cpa16h(&A[row * (KW * 2) + seg * 8], &g_xh[(m0 + row) * F_ + k0 + seg * 8]);
            cpa16h(&Bm[row * (KW * 2) + seg * 8], &Wp[(n0 + row) * F_ + k0 + seg * 8]);
        }
        CP_COMMIT();
    };

    float acc[2][4][4] = {};
    loadst(0, 0);
    loadst(1, 32);
    for (int i = 0; i < 8; i++) {
        CP_WAIT1();
        __syncthreads();
        const unsigned* Aw = (const unsigned*)stA(i % 3);
        const unsigned* Bw = (const unsigned*)stB(i % 3);
#pragma unroll
        for (int ks = 0; ks < 2; ks++) {
            int kw = ks * 8;
            unsigned a[2][4];
#pragma unroll
            for (int i2 = 0; i2 < 2; i2++) {
                int rb = wm + i2 * 16;
                a[i2][0] = Aw[(rb + g) * KW + kw + tg];
                a[i2][1] = Aw[(rb + g + 8) * KW + kw + tg];
                a[i2][2] = Aw[(rb + g) * KW + kw + tg + 4];
                a[i2][3] = Aw[(rb + g + 8) * KW + kw + tg + 4];
            }
#pragma unroll
            for (int j = 0; j < 4; j++) {
                unsigned b[2];
                b[0] = Bw[(wn + j * 8 + g) * KW + kw + tg];
                b[1] = Bw[(wn + j * 8 + g) * KW + kw + tg + 4];
                mma16(acc[0][j], a[0], b);
                mma16(acc[1][j], a[1], b);
            }
        }
        if (i + 2 < 8) loadst((i + 2) % 3, (i + 2) * 32);
        else CP_COMMIT();
    }

    // fused q/k partial dots (this block's 64 cols)
    float qp[2][2] = {}, kp[2][2] = {};
#pragma unroll
    for (int i2 = 0; i2 < 2; i2++)
#pragma unroll
        for (int j = 0; j < 4; j++) {
            int col = n0 + wn + j * 8 + tg * 2;
            float2 qv = *(const float2*)&q[col];
            float2 kv = *(const float2*)&kvec[col];
            qp[i2][0] += acc[i2][j][0] * qv.x + acc[i2][j][1] * qv.y;
            qp[i2][1] += acc[i2][j][2] * qv.x + acc[i2][j][3] * qv.y;
            kp[i2][0] += acc[i2][j][0] * kv.x + acc[i2][j][1] * kv.y;
            kp[i2][1] += acc[i2][j][2] * kv.x + acc[i2][j][3] * kv.y;
        }
#pragma unroll
    for (int o = 1; o < 4; o <<= 1)
#pragma unroll
        for (int i2 = 0; i2 < 2; i2++)
#pragma unroll
            for (int h = 0; h < 2; h++) {
                qp[i2][h] += __shfl_xor_sync(0xffffffffu, qp[i2][h], o);
                kp[i2][h] += __shfl_xor_sync(0xffffffffu, kp[i2][h], o);
            }
    if (tg == 0) {
#pragma unroll
        for (int i2 = 0; i2 < 2; i2++)
#pragma unroll
            for (int h = 0; h < 2; h++) {
                int row = m0 + wm + i2 * 16 + g + h * 8;
                atomicAdd(&g_qs[r * BN_ + row], qp[i2][h]);
                atomicAdd(&g_ks[r * BN_ + row], kp[i2][h]);
            }
    }

    // transposed H store via smem staging: T[64 e][80]
    __syncthreads();
    __half* T = (__half*)RAW;
#pragma unroll
    for (int i2 = 0; i2 < 2; i2++)
#pragma unroll
        for (int j = 0; j < 4; j++) {
            int cl = wn + j * 8 + tg * 2, rl = wm + i2 * 16 + g;
            T[cl * 80 + rl] = __float2half_rn(acc[i2][j][0]);
            T[(cl + 1) * 80 + rl] = __float2half_rn(acc[i2][j][1]);
            T[cl * 80 + rl + 8] = __float2half_rn(acc[i2][j][2]);
            T[(cl + 1) * 80 + rl + 8] = __float2half_rn(acc[i2][j][3]);
        }
    __syncthreads();
    size_t base = ((size_t)r * F_ + n0) * BN_ + m0;
#pragma unroll
    for (int u = 0; u < 4; u++) {
        int idx = t + u * 128;
        int row = idx >> 3, seg = idx & 7;
        *(uint4*)&g_Hh[base + (size_t)row * BN_ + seg * 8] = *(const uint4*)&T[row * 80 + seg * 8];
    }
}

// ---------------- attn: fused softmax + aggregation + relu(+bias) ----------------
// grid (4,4,8) x 128, block 32x64, warp 16x32, alpha whole-K in smem
__global__ __launch_bounds__(128) void attn_k(const float* __restrict__ convb) {
    int z = blockIdx.z, gg = z >> 1, dc = z & 1;
    int m0c = blockIdx.y * 32, n0 = blockIdx.x * 64;
    __shared__ __align__(16) __half AL[32 * 264];
    __shared__ __align__(16) unsigned char RAWB[3 * 5120];
    int t = threadIdx.x, lane = t & 31, warp = t >> 5;
    int wm = (warp >> 1) * 16, wn = (warp & 1) * 32;
    int g = lane >> 2, tg = lane & 3;

    auto stB = [&](int s) { return (__half*)(RAWB + s * 5120); };
    auto loadB = [&](int s, int k0) {
        __half* Bm = stB(s);
        int rel = (k0 >> 7) ^ dc;
        const __half* src = g_Hh + ((size_t)rel * F_ + n0) * BN_ + gg * N_ + k0;
#pragma unroll
        for (int u = 0; u < 2; u++) {
            int idx = t + u * 128;
            int row = idx >> 2, seg = idx & 3;
            cpa16h(&Bm[row * (KW * 2) + seg * 8], &src[(size_t)row * BN_ + seg * 8]);
        }
        CP_COMMIT();
    };
    loadB(0, 0);
    loadB(1, 32);

    // alpha: 4 warps x 8 rows
#pragma unroll
    for (int rr = 0; rr < 8; rr++) {
        int rl = warp * 8 + rr;
        int d = dc * 128 + m0c + rl;
        int nd = gg * N_ + d;
        float qs0 = g_qs[nd];
        float qs1 = g_qs[BN_ + nd];
        float l[8];
        float mx = -INFINITY;
#pragma unroll
        for (int j = 0; j < 8; j++) {
            int s = j * 32 + lane;
            int rel = (s >> 7) ^ dc;
            float ksv = g_ks[rel * BN_ + gg * N_ + s];
            float qv = rel ? qs1 : qs0;
            float v = qv + ksv;
            v = v >= 0.0f ? v : 0.2f * v;
            if (s == d) v = -INFINITY;
            l[j] = v;
            mx = fmaxf(mx, v);
        }
#pragma unroll
        for (int o = 16; o; o >>= 1) mx = fmaxf(mx, __shfl_xor_sync(0xffffffffu, mx, o));
        float sum = 0.0f;
#pragma unroll
        for (int j = 0; j < 8; j++) { l[j] = expf(l[j] - mx); sum += l[j]; }
#pragma unroll
        for (int o = 16; o; o >>= 1) sum += __shfl_xor_sync(0xffffffffu, sum, o);
        float inv = 1.0f / (sum + 1e-16f);
#pragma unroll
        for (int j = 0; j < 8; j++) AL[rl * 264 + j * 32 + lane] = __float2half_rn(l[j] * inv);
    }

    float acc[4][4] = {};
    const unsigned* ALw = (const unsigned*)AL;
    for (int i = 0; i < 8; i++) {
        CP_WAIT1();
        __syncthreads();
        const unsigned* Bw = (const unsigned*)stB(i % 3);
#pragma unroll
        for (int ks = 0; ks < 2; ks++) {
            int kwA = i * 16 + ks * 8, kwB = ks * 8;
            unsigned a[4];
            a[0] = ALw[(wm + g) * ALW + kwA + tg];
            a[1] = ALw[(wm + g + 8) * ALW + kwA + tg];
            a[2] = ALw[(wm + g) * ALW + kwA + tg + 4];
            a[3] = ALw[(wm + g + 8) * ALW + kwA + tg + 4];
#pragma unroll
            for (int j = 0; j < 4; j++) {
                unsigned b[2];
                b[0] = Bw[(wn + j * 8 + g) * KW + kwB + tg];
                b[1] = Bw[(wn + j * 8 + g) * KW + kwB + tg + 4];
                mma16(acc[j], a, b);
            }
        }
        if (i + 2 < 8) loadB((i + 2) % 3, (i + 2) * 32);
        else CP_COMMIT();
    }

    int node = gg * N_ + dc * 128 + m0c + wm + g;
#pragma unroll
    for (int j = 0; j < 4; j++) {
        int col = n0 + wn + j * 8 + tg * 2;
        float b0 = convb[col], b1 = convb[col + 1];
        *(__half2*)&g_m1h[(size_t)node * F_ + col] =
            __floats2half2_rn(fmaxf(acc[j][0] + b0, 0.f), fmaxf(acc[j][1] + b1, 0.f));
        *(__half2*)&g_m1h[(size_t)(node + 8) * F_ + col] =
            __floats2half2_rn(fmaxf(acc[j][2] + b0, 0.f), fmaxf(acc[j][3] + b1, 0.f));
    }
}

// ---------------- lin: msg2 = [x,msg1]@lin_w^T + b (fp32 out) + BN sums ----------------
// grid (4,32) x 128, block 32x64, warp 16x32, K=512
__global__ __launch_bounds__(128) void lin_k(int layer, const float* __restrict__ linb) {
    int m0 = blockIdx.y * 32, n0 = blockIdx.x * 64;
    __shared__ __align__(16) unsigned char RAW[3 * 7680];
    int t = threadIdx.x, lane = t & 31, warp = t >> 5;
    int wm = (warp >> 1) * 16, wn = (warp & 1) * 32;
    int g = lane >> 2, tg = lane & 3;
    const __half* lwp = g_lwh + (size_t)layer * F_ * 2 * F_;

    auto stA = [&](int s) { return (__half*)(RAW + s * 7680); };
    auto stB = [&](int s) { return (__half*)(RAW + s * 7680 + 2560); };
    auto loadst = [&](int s, int k0) {
        __half* Am = stA(s); __half* Bm = stB(s);
        {
            int row = t >> 2, seg = t & 3;
            const __half* Ab = (k0 < F_) ? &g_xh[(m0 + row) * F_ + k0 + seg * 8]
                                         : &g_m1h[(m0 + row) * F_ + (k0 - F_) + seg * 8];
            cpa16h(&Am[row * (KW * 2) + seg * 8], Ab);
        }
#pragma unroll
        for (int u = 0; u < 2; u++) {
            int idx = t + u * 128;
            int row = idx >> 2, seg = idx & 3;
            cpa16h(&Bm[row * (KW * 2) + seg * 8], &lwp[(size_t)(n0 + row) * 512 + k0 + seg * 8]);
        }
        CP_COMMIT();
    };

    float acc[4][4] = {};
    loadst(0, 0);
    loadst(1, 32);
    for (int i = 0; i < 16; i++) {
        CP_WAIT1();
        __syncthreads();
        const unsigned* Aw = (const unsigned*)stA(i % 3);
        const unsigned* Bw = (const unsigned*)stB(i % 3);
#pragma unroll
        for (int ks = 0; ks < 2; ks++) {
            int kw = ks * 8;
            unsigned a[4];
            a[0] = Aw[(wm + g) * KW + kw + tg];
            a[1] = Aw[(wm + g + 8) * KW + kw + tg];
            a[2] = Aw[(wm + g) * KW + kw + tg + 4];
            a[3] = Aw[(wm + g + 8) * KW + kw + tg + 4];
#pragma unroll
            for (int j = 0; j < 4; j++) {
                unsigned b[2];
                b[0] = Bw[(wn + j * 8 + g) * KW + kw + tg];
                b[1] = Bw[(wn + j * 8 + g) * KW + kw + tg + 4];
                mma16(acc[j], a, b);
            }
        }
        if (i + 2 < 16) loadst((i + 2) % 3, (i + 2) * 32);
        else CP_COMMIT();
    }

    int row = m0 + wm + g;
    float s0[4], s1[4], q0[4], q1[4];
#pragma unroll
    for (int j = 0; j < 4; j++) {
        int col = n0 + wn + j * 8 + tg * 2;
        float b0 = linb[col], b1 = linb[col + 1];
        float v0 = acc[j][0] + b0, v1 = acc[j][1] + b1;
        float v2 = acc[j][2] + b0, v3 = acc[j][3] + b1;
        *(float2*)&g_msg2[(size_t)row * F_ + col] = make_float2(v0, v1);
        *(float2*)&g_msg2[(size_t)(row + 8) * F_ + col] = make_float2(v2, v3);
        s0[j] = v0 + v2; s1[j] = v1 + v3;
        q0[j] = v0 * v0 + v2 * v2; q1[j] = v1 * v1 + v3 * v3;
    }
#pragma unroll
    for (int o = 4; o < 32; o <<= 1)
#pragma unroll
        for (int j = 0; j < 4; j++) {
            s0[j] += __shfl_xor_sync(0xffffffffu, s0[j], o);
            s1[j] += __shfl_xor_sync(0xffffffffu, s1[j], o);
            q0[j] += __shfl_xor_sync(0xffffffffu, q0[j], o);
            q1[j] += __shfl_xor_sync(0xffffffffu, q1[j], o);
        }
    if (g == 0) {
#pragma unroll
        for (int j = 0; j < 4; j++) {
            int col = n0 + wn + j * 8 + tg * 2;
            atomicAdd(&g_sum[col], s0[j]);
            atomicAdd(&g_sum[col + 1], s1[j]);
            atomicAdd(&g_sum2[col], q0[j]);
            atomicAdd(&g_sum2[col + 1], q1[j]);
        }
    }
}

// ---------------- batchnorm apply (computes mu/rstd inline) + residual ----------------
__global__ void bn_apply(const float* __restrict__ bw, const float* __restrict__ bb) {
    int c = threadIdx.x;
    float mu = g_sum[c] * (1.0f / BN_);
    float var = g_sum2[c] * (1.0f / BN_) - mu * mu;
    float rstd = rsqrtf(var + 1e-5f);
    int idx = blockIdx.x * F_ + c;
    float v = g_x[idx] + bw[c] * (g_msg2[idx] - mu) * rstd + bb[c];
    g_x[idx] = v;
    g_xh[idx] = __float2half_rn(v);
    if (blockIdx.x < 16) {
        int zi = blockIdx.x * 256 + c;
        if (zi < 2048) g_qs[zi] = 0.f;
        else           g_ks[zi - 2048] = 0.f;
    }
}

// ---------------- unpack ----------------
__global__ void unpack_kernel(float* __restrict__ out) {
    int b = blockIdx.x >> 8;
    int n = blockIdx.x & 255;
    int f = threadIdx.x;
    float v = g_x[(b * N_ + n) * F_ + f];
    if (n < N0_) out[(b * F_ + f) * N0_ + n] = v;
    else         out[B_ * F_ * N0_ + (b * F_ + f) * N0_ + (n - N0_)] = v;
}

// ---------------- host ----------------
extern "C" void kernel_launch(void* const* d_in, const int* in_sizes, int n_in,
                              void* d_out, int out_size) {
    const float* desc0  = (const float*)d_in[0];
    const float* desc1  = (const float*)d_in[1];
    const float* conv_w = (const float*)d_in[2];
    const float* conv_q = (const float*)d_in[3];
    const float* conv_k = (const float*)d_in[4];
    const float* conv_b = (const float*)d_in[5];
    const float* lin_w  = (const float*)d_in[6];
    const float* lin_b  = (const float*)d_in[7];
    const float* bn_w   = (const float*)d_in[8];
    const float* bn_b   = (const float*)d_in[9];
    float* out = (float*)d_out;

    prep_kernel<<<2176, 256>>>(desc0, desc1, conv_w, lin_w);

    for (int i = 0; i < L_; i++) {
        gemm_H_k<<<dim3(4, 16, 2), 128>>>(i, conv_q + i * F_, conv_k + i * F_);
        attn_k<<<dim3(4, 4, 8), 128>>>(conv_b + i * F_);
        lin_k<<<dim3(4, 32), 128>>>(i, lin_b + i * F_);
        bn_apply<<<BN_, F_>>>(bn_w + i * F_, bn_b + i * F_);
    }

    unpack_kernel<<<BN_, F_>>>(out);
}

// round 13
// speedup vs baseline: 2.3437x; 1.0334x over previous
#include <cuda_runtime.h>
#include <cuda_fp16.h>
#include <math.h>

// ---------------- problem constants ----------------
#define B_   4
#define F_   256
#define N0_  128
#define N_   256
#define BN_  1024
#define L_   3

#define KW  20     // 32-bit words per 32-half smem row (16 data + 4 pad) -> conflict-free
#define ALW 132    // 32-bit words per 256-half alpha row (264 halves)

// ---------------- scratch ----------------
__device__ float  g_x[BN_ * F_];          // exact features
__device__ __half g_xh[BN_ * F_];         // half features
__device__ __half g_Hh[2 * F_ * BN_];     // H transposed: [r][e][node]
__device__ __half g_Wh[L_ * 2 * F_ * F_]; // conv W transposed: [l][r][e][f]
__device__ __half g_lwh[L_ * F_ * 2 * F_];// lin W: [l][o][k] (natural layout)
__device__ __half g_m1h[BN_ * F_];        // msg1 half [node][feat]
__device__ float  g_msg2[BN_ * F_];
__device__ float  g_qs[2 * BN_], g_ks[2 * BN_];
__device__ float  g_sum[F_], g_sum2[F_];

// ---------------- helpers ----------------
__device__ __forceinline__ void mma16(float* d, const unsigned* a, const unsigned* b) {
    asm volatile(
        "mma.sync.aligned.m16n8k16.row.col.f32.f16.f16.f32 "
        "{%0,%1,%2,%3},{%4,%5,%6,%7},{%8,%9},{%0,%1,%2,%3};\n"
        : "+f"(d[0]), "+f"(d[1]), "+f"(d[2]), "+f"(d[3])
        : "r"(a[0]), "r"(a[1]), "r"(a[2]), "r"(a[3]), "r"(b[0]), "r"(b[1]));
}

__device__ __forceinline__ void cpa16h(__half* s, const __half* g) {
    unsigned ss = (unsigned)__cvta_generic_to_shared(s);
    asm volatile("cp.async.cg.shared.global [%0], [%1], 16;\n" :: "r"(ss), "l"(g));
}
#define CP_COMMIT() asm volatile("cp.async.commit_group;\n")
#define CP_WAIT1()  asm volatile("cp.async.wait_group 1;\n")

// ---------------- prep: pack + zero + round/transpose weights ----------------
__global__ void prep_kernel(const float* __restrict__ d0, const float* __restrict__ d1,
                            const float* __restrict__ cw, const float* __restrict__ lw) {
    __shared__ float s[32][33];
    int bid = blockIdx.x, t = threadIdx.x;
    if (bid < 1024) {
        int b = bid >> 8, n = bid & 255;
        float v = (n < N0_) ? d0[(b * F_ + t) * N0_ + n]
                            : d1[(b * F_ + t) * N0_ + (n - N0_)];
        int idx = (b * N_ + n) * F_ + t;
        g_x[idx] = v;
        g_xh[idx] = __float2half_rn(v);
        if (bid < 18) {
            int zi = bid * 256 + t;
            if (zi < 2048)       g_qs[zi] = 0.f;
            else if (zi < 4096)  g_ks[zi - 2048] = 0.f;
            else if (zi < 4352)  g_sum[zi - 4096] = 0.f;
            else                 g_sum2[zi - 4352] = 0.f;
        }
    } else if (bid < 1408) {
        int tt = bid - 1024, mat = tt >> 6, tile = tt & 63;
        int fr = (tile >> 3) * 32, ec = (tile & 7) * 32;
        int tx = t & 31, ty = t >> 5;
        for (int i = ty; i < 32; i += 8) s[i][tx] = cw[(mat * F_ + fr + i) * F_ + ec + tx];
        __syncthreads();
        for (int i = ty; i < 32; i += 8)
            g_Wh[((size_t)mat * F_ + ec + i) * F_ + fr + tx] = __float2half_rn(s[tx][i]);
    } else {
        size_t i0 = (size_t)(bid - 1408) * 512 + t;
        g_lwh[i0] = __float2half_rn(lw[i0]);
        g_lwh[i0 + 256] = __float2half_rn(lw[i0 + 256]);
    }
}

// ---------------- gemm_H: H[r]^T = (x@W[r])^T + fused q/k scores ----------------
// grid (4,16,2) x 128, block 64x64, warp 32x32, BK=32, 3-stage cp.async
__global__ __launch_bounds__(128) void gemm_H_k(int layer, const float* __restrict__ q,
                                                const float* __restrict__ kvec) {
    int r = blockIdx.z;
    int m0 = blockIdx.y * 64, n0 = blockIdx.x * 64;
    __shared__ __align__(16) unsigned char RAW[3 * 10240];
    int t = threadIdx.x, lane = t & 31, warp = t >> 5;
    int wm = (warp >> 1) * 32, wn = (warp & 1) * 32;
    int g = lane >> 2, tg = lane & 3;
    const __half* Wp = g_Wh + (size_t)(layer * 2 + r) * F_ * F_;

    if (blockIdx.x == 0 && blockIdx.y == 0 && blockIdx.z == 0) {
        for (int i = t; i < F_; i += 128) { g_sum[i] = 0.f; g_sum2[i] = 0.f; }
    }

    auto stA = [&](int s) { return (__half*)(RAW + s * 10240); };
    auto stB = [&](int s) { return (__half*)(RAW + s * 10240 + 5120); };
    auto loadst = [&](int s, int k0) {
        __half* A = stA(s); __half* Bm = stB(s);
#pragma unroll
        for (int u = 0; u < 2; u++) {
            int idx = t + u * 128;
            int row = idx >> 2, seg = idx & 3;
            cpa16h(&A[row * (KW * 2) + seg * 8], &g_xh[(m0 + row) * F_ + k0 + seg * 8]);
            cpa16h(&Bm[row * (KW * 2) + seg * 8], &Wp[(n0 + row) * F_ + k0 + seg * 8]);
        }
        CP_COMMIT();
    };

    float acc[2][4][4] = {};
    loadst(0, 0);
    loadst(1, 32);
    for (int i = 0; i < 8; i++) {
        CP_WAIT1();
        __syncthreads();
        const unsigned* Aw = (const unsigned*)stA(i % 3);
        const unsigned* Bw = (const unsigned*)stB(i % 3);
#pragma unroll
        for (int ks = 0; ks < 2; ks++) {
            int kw = ks * 8;
            unsigned a[2][4];
#pragma unroll
            for (int i2 = 0; i2 < 2; i2++) {
                int rb = wm + i2 * 16;
                a[i2][0] = Aw[(rb + g) * KW + kw + tg];
                a[i2][1] = Aw[(rb + g + 8) * KW + kw + tg];
                a[i2][2] = Aw[(rb + g) * KW + kw + tg + 4];
                a[i2][3] = Aw[(rb + g + 8) * KW + kw + tg + 4];
            }
#pragma unroll
            for (int j = 0; j < 4; j++) {
                unsigned b[2];
                b[0] = Bw[(wn + j * 8 + g) * KW + kw + tg];
                b[1] = Bw[(wn + j * 8 + g) * KW + kw + tg + 4];
                mma16(acc[0][j], a[0], b);
                mma16(acc[1][j], a[1], b);
            }
        }
        if (i + 2 < 8) loadst((i + 2) % 3, (i + 2) * 32);
        else CP_COMMIT();
    }

    // fused q/k partial dots (this block's 64 cols)
    float qp[2][2] = {}, kp[2][2] = {};
#pragma unroll
    for (int i2 = 0; i2 < 2; i2++)
#pragma unroll
        for (int j = 0; j < 4; j++) {
            int col = n0 + wn + j * 8 + tg * 2;
            float2 qv = *(const float2*)&q[col];
            float2 kv = *(const float2*)&kvec[col];
            qp[i2][0] += acc[i2][j][0] * qv.x + acc[i2][j][1] * qv.y;
            qp[i2][1] += acc[i2][j][2] * qv.x + acc[i2][j][3] * qv.y;
            kp[i2][0] += acc[i2][j][0] * kv.x + acc[i2][j][1] * kv.y;
            kp[i2][1] += acc[i2][j][2] * kv.x + acc[i2][j][3] * kv.y;
        }
#pragma unroll
    for (int o = 1; o < 4; o <<= 1)
#pragma unroll
        for (int i2 = 0; i2 < 2; i2++)
#pragma unroll
            for (int h = 0; h < 2; h++) {
                qp[i2][h] += __shfl_xor_sync(0xffffffffu, qp[i2][h], o);
                kp[i2][h] += __shfl_xor_sync(0xffffffffu, kp[i2][h], o);
            }
    if (tg == 0) {
#pragma unroll
        for (int i2 = 0; i2 < 2; i2++)
#pragma unroll
            for (int h = 0; h < 2; h++) {
                int row = m0 + wm + i2 * 16 + g + h * 8;
                atomicAdd(&g_qs[r * BN_ + row], qp[i2][h]);
                atomicAdd(&g_ks[r * BN_ + row], kp[i2][h]);
            }
    }

    // transposed H store via smem staging: T[64 e][80]
    __syncthreads();
    __half* T = (__half*)RAW;
#pragma unroll
    for (int i2 = 0; i2 < 2; i2++)
#pragma unroll
        for (int j = 0; j < 4; j++) {
            int cl = wn + j * 8 + tg * 2, rl = wm + i2 * 16 + g;
            T[cl * 80 + rl] = __float2half_rn(acc[i2][j][0]);
            T[(cl + 1) * 80 + rl] = __float2half_rn(acc[i2][j][1]);
            T[cl * 80 + rl + 8] = __float2half_rn(acc[i2][j][2]);
            T[(cl + 1) * 80 + rl + 8] = __float2half_rn(acc[i2][j][3]);
        }
    __syncthreads();
    size_t base = ((size_t)r * F_ + n0) * BN_ + m0;
#pragma unroll
    for (int u = 0; u < 4; u++) {
        int idx = t + u * 128;
        int row = idx >> 3, seg = idx & 7;
        *(uint4*)&g_Hh[base + (size_t)row * BN_ + seg * 8] = *(const uint4*)&T[row * 80 + seg * 8];
    }
}

// ---------------- attn: fused softmax + aggregation + relu(+bias) ----------------
// grid (4,4,8) x 128, block 32x64, warp 16x32, alpha whole-K in smem
__global__ __launch_bounds__(128) void attn_k(const float* __restrict__ convb) {
    int z = blockIdx.z, gg = z >> 1, dc = z & 1;
    int m0c = blockIdx.y * 32, n0 = blockIdx.x * 64;
    __shared__ __align__(16) __half AL[32 * 264];
    __shared__ __align__(16) unsigned char RAWB[3 * 5120];
    int t = threadIdx.x, lane = t & 31, warp = t >> 5;
    int wm = (warp >> 1) * 16, wn = (warp & 1) * 32;
    int g = lane >> 2, tg = lane & 3;

    auto stB = [&](int s) { return (__half*)(RAWB + s * 5120); };
    auto loadB = [&](int s, int k0) {
        __half* Bm = stB(s);
        int rel = (k0 >> 7) ^ dc;
        const __half* src = g_Hh + ((size_t)rel * F_ + n0) * BN_ + gg * N_ + k0;
#pragma unroll
        for (int u = 0; u < 2; u++) {
            int idx = t + u * 128;
            int row = idx >> 2, seg = idx & 3;
            cpa16h(&Bm[row * (KW * 2) + seg * 8], &src[(size_t)row * BN_ + seg * 8]);
        }
        CP_COMMIT();
    };
    loadB(0, 0);
    loadB(1, 32);

    // alpha: 4 warps x 8 rows
#pragma unroll
    for (int rr = 0; rr < 8; rr++) {
        int rl = warp * 8 + rr;
        int d = dc * 128 + m0c + rl;
        int nd = gg * N_ + d;
        float qs0 = g_qs[nd];
        float qs1 = g_qs[BN_ + nd];
        float l[8];
        float mx = -INFINITY;
#pragma unroll
        for (int j = 0; j < 8; j++) {
            int s = j * 32 + lane;
            int rel = (s >> 7) ^ dc;
            float ksv = g_ks[rel * BN_ + gg * N_ + s];
            float qv = rel ? qs1 : qs0;
            float v = qv + ksv;
            v = v >= 0.0f ? v : 0.2f * v;
            if (s == d) v = -INFINITY;
            l[j] = v;
            mx = fmaxf(mx, v);
        }
#pragma unroll
        for (int o = 16; o; o >>= 1) mx = fmaxf(mx, __shfl_xor_sync(0xffffffffu, mx, o));
        float sum = 0.0f;
#pragma unroll
        for (int j = 0; j < 8; j++) { l[j] = expf(l[j] - mx); sum += l[j]; }
#pragma unroll
        for (int o = 16; o; o >>= 1) sum += __shfl_xor_sync(0xffffffffu, sum, o);
        float inv = 1.0f / (sum + 1e-16f);
#pragma unroll
        for (int j = 0; j < 8; j++) AL[rl * 264 + j * 32 + lane] = __float2half_rn(l[j] * inv);
    }

    float acc[4][4] = {};
    const unsigned* ALw = (const unsigned*)AL;
    for (int i = 0; i < 8; i++) {
        CP_WAIT1();
        __syncthreads();
        const unsigned* Bw = (const unsigned*)stB(i % 3);
#pragma unroll
        for (int ks = 0; ks < 2; ks++) {
            int kwA = i * 16 + ks * 8, kwB = ks * 8;
            unsigned a[4];
            a[0] = ALw[(wm + g) * ALW + kwA + tg];
            a[1] = ALw[(wm + g + 8) * ALW + kwA + tg];
            a[2] = ALw[(wm + g) * ALW + kwA + tg + 4];
            a[3] = ALw[(wm + g + 8) * ALW + kwA + tg + 4];
#pragma unroll
            for (int j = 0; j < 4; j++) {
                unsigned b[2];
                b[0] = Bw[(wn + j * 8 + g) * KW + kwB + tg];
                b[1] = Bw[(wn + j * 8 + g) * KW + kwB + tg + 4];
                mma16(acc[j], a, b);
            }
        }
        if (i + 2 < 8) loadB((i + 2) % 3, (i + 2) * 32);
        else CP_COMMIT();
    }

    int node = gg * N_ + dc * 128 + m0c + wm + g;
#pragma unroll
    for (int j = 0; j < 4; j++) {
        int col = n0 + wn + j * 8 + tg * 2;
        float b0 = convb[col], b1 = convb[col + 1];
        *(__half2*)&g_m1h[(size_t)node * F_ + col] =
            __floats2half2_rn(fmaxf(acc[j][0] + b0, 0.f), fmaxf(acc[j][1] + b1, 0.f));
        *(__half2*)&g_m1h[(size_t)(node + 8) * F_ + col] =
            __floats2half2_rn(fmaxf(acc[j][2] + b0, 0.f), fmaxf(acc[j][3] + b1, 0.f));
    }
}

// ---------------- lin: msg2 = [x,msg1]@lin_w^T + b (fp32 out) + BN sums ----------------
// grid (4,32) x 128, block 32x64, warp 16x32, K=512
__global__ __launch_bounds__(128) void lin_k(int layer, const float* __restrict__ linb) {
    int m0 = blockIdx.y * 32, n0 = blockIdx.x * 64;
    __shared__ __align__(16) unsigned char RAW[3 * 7680];
    int t = threadIdx.x, lane = t & 31, warp = t >> 5;
    int wm = (warp >> 1) * 16, wn = (warp & 1) * 32;
    int g = lane >> 2, tg = lane & 3;
    const __half* lwp = g_lwh + (size_t)layer * F_ * 2 * F_;

    auto stA = [&](int s) { return (__half*)(RAW + s * 7680); };
    auto stB = [&](int s) { return (__half*)(RAW + s * 7680 + 2560); };
    auto loadst = [&](int s, int k0) {
        __half* Am = stA(s); __half* Bm = stB(s);
        {
            int row = t >> 2, seg = t & 3;
            const __half* Ab = (k0 < F_) ? &g_xh[(m0 + row) * F_ + k0 + seg * 8]
                                         : &g_m1h[(m0 + row) * F_ + (k0 - F_) + seg * 8];
            cpa16h(&Am[row * (KW * 2) + seg * 8], Ab);
        }
#pragma unroll
        for (int u = 0; u < 2; u++) {
            int idx = t + u * 128;
            int row = idx >> 2, seg = idx & 3;
            cpa16h(&Bm[row * (KW * 2) + seg * 8], &lwp[(size_t)(n0 + row) * 512 + k0 + seg * 8]);
        }
        CP_COMMIT();
    };

    float acc[4][4] = {};
    loadst(0, 0);
    loadst(1, 32);
    for (int i = 0; i < 16; i++) {
        CP_WAIT1();
        __syncthreads();
        const unsigned* Aw = (const unsigned*)stA(i % 3);
        const unsigned* Bw = (const unsigned*)stB(i % 3);
#pragma unroll
        for (int ks = 0; ks < 2; ks++) {
            int kw = ks * 8;
            unsigned a[4];
            a[0] = Aw[(wm + g) * KW + kw + tg];
            a[1] = Aw[(wm + g + 8) * KW + kw + tg];
            a[2] = Aw[(wm + g) * KW + kw + tg + 4];
            a[3] = Aw[(wm + g + 8) * KW + kw + tg + 4];
#pragma unroll
            for (int j = 0; j < 4; j++) {
                unsigned b[2];
                b[0] = Bw[(wn + j * 8 + g) * KW + kw + tg];
                b[1] = Bw[(wn + j * 8 + g) * KW + kw + tg + 4];
                mma16(acc[j], a, b);
            }
        }
        if (i + 2 < 16) loadst((i + 2) % 3, (i + 2) * 32);
        else CP_COMMIT();
    }

    int row = m0 + wm + g;
    float s0[4], s1[4], q0[4], q1[4];
#pragma unroll
    for (int j = 0; j < 4; j++) {
        int col = n0 + wn + j * 8 + tg * 2;
        float b0 = linb[col], b1 = linb[col + 1];
        float v0 = acc[j][0] + b0, v1 = acc[j][1] + b1;
        float v2 = acc[j][2] + b0, v3 = acc[j][3] + b1;
        *(float2*)&g_msg2[(size_t)row * F_ + col] = make_float2(v0, v1);
        *(float2*)&g_msg2[(size_t)(row + 8) * F_ + col] = make_float2(v2, v3);
        s0[j] = v0 + v2; s1[j] = v1 + v3;
        q0[j] = v0 * v0 + v2 * v2; q1[j] = v1 * v1 + v3 * v3;
    }
#pragma unroll
    for (int o = 4; o < 32; o <<= 1)
#pragma unroll
        for (int j = 0; j < 4; j++) {
            s0[j] += __shfl_xor_sync(0xffffffffu, s0[j], o);
            s1[j] += __shfl_xor_sync(0xffffffffu, s1[j], o);
            q0[j] += __shfl_xor_sync(0xffffffffu, q0[j], o);
            q1[j] += __shfl_xor_sync(0xffffffffu, q1[j], o);
        }
    if (g == 0) {
#pragma unroll
        for (int j = 0; j < 4; j++) {
            int col = n0 + wn + j * 8 + tg * 2;
            atomicAdd(&g_sum[col], s0[j]);
            atomicAdd(&g_sum[col + 1], s1[j]);
            atomicAdd(&g_sum2[col], q0[j]);
            atomicAdd(&g_sum2[col + 1], q1[j]);
        }
    }
}

// ---------------- batchnorm apply (computes mu/rstd inline) + residual ----------------
__global__ void bn_apply(const float* __restrict__ bw, const float* __restrict__ bb) {
    int c = threadIdx.x;
    float mu = g_sum[c] * (1.0f / BN_);
    float var = g_sum2[c] * (1.0f / BN_) - mu * mu;
    float rstd = rsqrtf(var + 1e-5f);
    int idx = blockIdx.x * F_ + c;
    float v = g_x[idx] + bw[c] * (g_msg2[idx] - mu) * rstd + bb[c];
    g_x[idx] = v;
    g_xh[idx] = __float2half_rn(v);
    if (blockIdx.x < 16) {
        int zi = blockIdx.x * 256 + c;
        if (zi < 2048) g_qs[zi] = 0.f;
        else           g_ks[zi - 2048] = 0.f;
    }
}

// ---------------- unpack ----------------
__global__ void unpack_kernel(float* __restrict__ out) {
    int b = blockIdx.x >> 8;
    int n = blockIdx.x & 255;
    int f = threadIdx.x;
    float v = g_x[(b * N_ + n) * F_ + f];
    if (n < N0_) out[(b * F_ + f) * N0_ + n] = v;
    else         out[B_ * F_ * N0_ + (b * F_ + f) * N0_ + (n - N0_)] = v;
}

// ---------------- host ----------------
extern "C" void kernel_launch(void* const* d_in, const int* in_sizes, int n_in,
                              void* d_out, int out_size) {
    const float* desc0  = (const float*)d_in[0];
    const float* desc1  = (const float*)d_in[1];
    const float* conv_w = (const float*)d_in[2];
    const float* conv_q = (const float*)d_in[3];
    const float* conv_k = (const float*)d_in[4];
    const float* conv_b = (const float*)d_in[5];
    const float* lin_w  = (const float*)d_in[6];
    const float* lin_b  = (const float*)d_in[7];
    const float* bn_w   = (const float*)d_in[8];
    const float* bn_b   = (const float*)d_in[9];
    float* out = (float*)d_out;

    prep_kernel<<<2176, 256>>>(desc0, desc1, conv_w, lin_w);

    for (int i = 0; i < L_; i++) {
        gemm_H_k<<<dim3(4, 16, 2), 128>>>(i, conv_q + i * F_, conv_k + i * F_);
        attn_k<<<dim3(4, 4, 8), 128>>>(conv_b + i * F_);
        lin_k<<<dim3(4, 32), 128>>>(i, lin_b + i * F_);
        bn_apply<<<BN_, F_>>>(bn_w + i * F_, bn_b + i * F_);
    }

    unpack_kernel<<<BN_, F_>>>(out);
}

// round 14
// speedup vs baseline: 2.5023x; 1.0677x over previous
#include <cuda_runtime.h>
#include <cuda_fp16.h>
#include <math.h>

// ---------------- problem constants ----------------
#define B_   4
#define F_   256
#define N0_  128
#define N_   256
#define BN_  1024
#define L_   3

#define KW  20     // 32-bit words per 32-half smem row (16 data + 4 pad) -> conflict-free
#define ALW 132    // 32-bit words per 256-half alpha row (264 halves)

// ---------------- scratch ----------------
__device__ float  g_x[BN_ * F_];          // exact features
__device__ __half g_xh[BN_ * F_];         // half features
__device__ __half g_Hh[2 * F_ * BN_];     // H transposed: [r][e][node]
__device__ __half g_Wh[L_ * 2 * F_ * F_]; // conv W transposed: [l][r][e][f]
__device__ __half g_lwh[L_ * F_ * 2 * F_];// lin W: [l][o][k]
__device__ __half g_m1h[BN_ * F_];        // msg1 half [node][feat]
__device__ float  g_msg2[BN_ * F_];
__device__ float  g_qs[2 * BN_], g_ks[2 * BN_];
__device__ float  g_sum[F_], g_sum2[F_];

// ---------------- helpers ----------------
__device__ __forceinline__ void mma16(float* d, const unsigned* a, const unsigned* b) {
    asm volatile(
        "mma.sync.aligned.m16n8k16.row.col.f32.f16.f16.f32 "
        "{%0,%1,%2,%3},{%4,%5,%6,%7},{%8,%9},{%0,%1,%2,%3};\n"
        : "+f"(d[0]), "+f"(d[1]), "+f"(d[2]), "+f"(d[3])
        : "r"(a[0]), "r"(a[1]), "r"(a[2]), "r"(a[3]), "r"(b[0]), "r"(b[1]));
}

__device__ __forceinline__ void cpa16h(__half* s, const __half* g) {
    unsigned ss = (unsigned)__cvta_generic_to_shared(s);
    asm volatile("cp.async.cg.shared.global [%0], [%1], 16;\n" :: "r"(ss), "l"(g));
}
#define CP_COMMIT() asm volatile("cp.async.commit_group;\n")
#define CP_WAIT1()  asm volatile("cp.async.wait_group 1;\n")

// ---------------- prep: pack + zero + round/transpose weights ----------------
__global__ void prep_kernel(const float* __restrict__ d0, const float* __restrict__ d1,
                            const float* __restrict__ cw, const float* __restrict__ lw) {
    __shared__ float s[32][33];
    int bid = blockIdx.x, t = threadIdx.x;
    if (bid < 1024) {
        int b = bid >> 8, n = bid & 255;
        float v = (n < N0_) ? d0[(b * F_ + t) * N0_ + n]
                            : d1[(b * F_ + t) * N0_ + (n - N0_)];
        int idx = (b * N_ + n) * F_ + t;
        g_x[idx] = v;
        g_xh[idx] = __float2half_rn(v);
        if (bid < 18) {
            int zi = bid * 256 + t;
            if (zi < 2048)       g_qs[zi] = 0.f;
            else if (zi < 4096)  g_ks[zi - 2048] = 0.f;
            else if (zi < 4352)  g_sum[zi - 4096] = 0.f;
            else                 g_sum2[zi - 4352] = 0.f;
        }
    } else if (bid < 1408) {
        int tt = bid - 1024, mat = tt >> 6, tile = tt & 63;
        int fr = (tile >> 3) * 32, ec = (tile & 7) * 32;
        int tx = t & 31, ty = t >> 5;
        for (int i = ty; i < 32; i += 8) s[i][tx] = cw[(mat * F_ + fr + i) * F_ + ec + tx];
        __syncthreads();
        for (int i = ty; i < 32; i += 8)
            g_Wh[((size_t)mat * F_ + ec + i) * F_ + fr + tx] = __float2half_rn(s[tx][i]);
    } else {
        size_t i0 = (size_t)(bid - 1408) * 512 + t;
        g_lwh[i0] = __float2half_rn(lw[i0]);
        g_lwh[i0 + 256] = __float2half_rn(lw[i0 + 256]);
    }
}

// ---------------- gemm_H: H[r]^T = (x@W[r])^T + fused q/k scores ----------------
// grid (4,16,2) x 256, block 64x64, 2 K-groups x 4 warps (32x32 tiles), BK=64/stage
__global__ __launch_bounds__(256) void gemm_H_k(int layer, const float* __restrict__ q,
                                                const float* __restrict__ kvec) {
    extern __shared__ __align__(16) unsigned char RAW[];
    int r = blockIdx.z;
    int m0 = blockIdx.y * 64, n0 = blockIdx.x * 64;
    int t = threadIdx.x, lane = t & 31, warp = t >> 5;
    int kh = warp >> 2, wq = warp & 3;
    int wm = (wq >> 1) * 32, wn = (wq & 1) * 32;
    int g = lane >> 2, tg = lane & 3;
    const __half* Wp = g_Wh + (size_t)(layer * 2 + r) * F_ * F_;

    if (blockIdx.x == 0 && blockIdx.y == 0 && blockIdx.z == 0) {
        for (int i = t; i < F_; i += 256) { g_sum[i] = 0.f; g_sum2[i] = 0.f; }
    }

    auto stA = [&](int s, int h) { return (__half*)(RAW + s * 20480 + h * 5120); };
    auto stB = [&](int s, int h) { return (__half*)(RAW + s * 20480 + 10240 + h * 5120); };
    auto loadst = [&](int s, int k0) {
#pragma unroll
        for (int u = 0; u < 2; u++) {
            int idx = t + u * 256;
            int h = idx >> 8, rr = (idx >> 2) & 63, seg = idx & 3;
            cpa16h(stA(s, h) + rr * (KW * 2) + seg * 8, &g_xh[(m0 + rr) * F_ + k0 + h * 32 + seg * 8]);
        }
#pragma unroll
        for (int u = 0; u < 2; u++) {
            int idx = t + u * 256;
            int h = idx >> 8, rr = (idx >> 2) & 63, seg = idx & 3;
            cpa16h(stB(s, h) + rr * (KW * 2) + seg * 8, &Wp[(n0 + rr) * F_ + k0 + h * 32 + seg * 8]);
        }
        CP_COMMIT();
    };

    float acc[2][4][4] = {};
    loadst(0, 0);
    loadst(1, 64);
    for (int i = 0; i < 4; i++) {
        CP_WAIT1();
        __syncthreads();
        const unsigned* Aw = (const unsigned*)stA(i % 3, kh);
        const unsigned* Bw = (const unsigned*)stB(i % 3, kh);
#pragma unroll
        for (int ks = 0; ks < 2; ks++) {
            int kw = ks * 8;
            unsigned a[2][4];
#pragma unroll
            for (int i2 = 0; i2 < 2; i2++) {
                int rb = wm + i2 * 16;
                a[i2][0] = Aw[(rb + g) * KW + kw + tg];
                a[i2][1] = Aw[(rb + g + 8) * KW + kw + tg];
                a[i2][2] = Aw[(rb + g) * KW + kw + tg + 4];
                a[i2][3] = Aw[(rb + g + 8) * KW + kw + tg + 4];
            }
#pragma unroll
            for (int j = 0; j < 4; j++) {
                unsigned b[2];
                b[0] = Bw[(wn + j * 8 + g) * KW + kw + tg];
                b[1] = Bw[(wn + j * 8 + g) * KW + kw + tg + 4];
                mma16(acc[0][j], a[0], b);
                mma16(acc[1][j], a[1], b);
            }
        }
        if (i + 2 < 4) loadst((i + 2) % 3, (i + 2) * 64);
        else CP_COMMIT();
    }

    // cross-group reduction (deterministic order: group0 += group1)
    __syncthreads();
    float* red = (float*)RAW;
    if (kh == 1) {
        float* p = red + (wq * 32 + lane) * 32;
#pragma unroll
        for (int i2 = 0; i2 < 2; i2++)
#pragma unroll
            for (int j = 0; j < 4; j++)
#pragma unroll
                for (int e = 0; e < 4; e++) p[i2 * 16 + j * 4 + e] = acc[i2][j][e];
    }
    __syncthreads();
    if (kh == 0) {
        const float* p = red + (wq * 32 + lane) * 32;
#pragma unroll
        for (int i2 = 0; i2 < 2; i2++)
#pragma unroll
            for (int j = 0; j < 4; j++)
#pragma unroll
                for (int e = 0; e < 4; e++) acc[i2][j][e] += p[i2 * 16 + j * 4 + e];

        // fused q/k partial dots (this block's 64 cols)
        float qp[2][2] = {}, kp[2][2] = {};
#pragma unroll
        for (int i2 = 0; i2 < 2; i2++)
#pragma unroll
            for (int j = 0; j < 4; j++) {
                int col = n0 + wn + j * 8 + tg * 2;
                float2 qv = *(const float2*)&q[col];
                float2 kv = *(const float2*)&kvec[col];
                qp[i2][0] += acc[i2][j][0] * qv.x + acc[i2][j][1] * qv.y;
                qp[i2][1] += acc[i2][j][2] * qv.x + acc[i2][j][3] * qv.y;
                kp[i2][0] += acc[i2][j][0] * kv.x + acc[i2][j][1] * kv.y;
                kp[i2][1] += acc[i2][j][2] * kv.x + acc[i2][j][3] * kv.y;
            }
#pragma unroll
        for (int o = 1; o < 4; o <<= 1)
#pragma unroll
            for (int i2 = 0; i2 < 2; i2++)
#pragma unroll
                for (int h = 0; h < 2; h++) {
                    qp[i2][h] += __shfl_xor_sync(0xffffffffu, qp[i2][h], o);
                    kp[i2][h] += __shfl_xor_sync(0xffffffffu, kp[i2][h], o);
                }
        if (tg == 0) {
#pragma unroll
            for (int i2 = 0; i2 < 2; i2++)
#pragma unroll
                for (int h = 0; h < 2; h++) {
                    int row = m0 + wm + i2 * 16 + g + h * 8;
                    atomicAdd(&g_qs[r * BN_ + row], qp[i2][h]);
                    atomicAdd(&g_ks[r * BN_ + row], kp[i2][h]);
                }
        }
    }
    __syncthreads();
    // transposed H store via smem staging: T[64 e][80]
    __half* T = (__half*)(RAW + 16384);
    if (kh == 0) {
#pragma unroll
        for (int i2 = 0; i2 < 2; i2++)
#pragma unroll
            for (int j = 0; j < 4; j++) {
                int cl = wn + j * 8 + tg * 2, rl = wm + i2 * 16 + g;
                T[cl * 80 + rl] = __float2half_rn(acc[i2][j][0]);
                T[(cl + 1) * 80 + rl] = __float2half_rn(acc[i2][j][1]);
                T[cl * 80 + rl + 8] = __float2half_rn(acc[i2][j][2]);
                T[(cl + 1) * 80 + rl + 8] = __float2half_rn(acc[i2][j][3]);
            }
    }
    __syncthreads();
    size_t base = ((size_t)r * F_ + n0) * BN_ + m0;
#pragma unroll
    for (int u = 0; u < 2; u++) {
        int idx = t + u * 256;
        int row = idx >> 3, seg = idx & 7;
        *(uint4*)&g_Hh[base + (size_t)row * BN_ + seg * 8] = *(const uint4*)&T[row * 80 + seg * 8];
    }
}

// ---------------- attn: fused softmax + aggregation + relu(+bias) ----------------
// grid (4,4,8) x 256, block 32x64, 2 K-groups x 4 warps (16x32 tiles), alpha whole-K smem
__global__ __launch_bounds__(256) void attn_k(const float* __restrict__ convb) {
    int z = blockIdx.z, gg = z >> 1, dc = z & 1;
    int m0c = blockIdx.y * 32, n0 = blockIdx.x * 64;
    __shared__ __align__(16) __half AL[32 * 264];
    __shared__ __align__(16) unsigned char RAWB[3 * 10240];
    int t = threadIdx.x, lane = t & 31, warp = t >> 5;
    int kh = warp >> 2, wq = warp & 3;
    int wm = (wq >> 1) * 16, wn = (wq & 1) * 32;
    int g = lane >> 2, tg = lane & 3;

    auto stB = [&](int s, int h) { return (__half*)(RAWB + s * 10240 + h * 5120); };
    auto loadB = [&](int s, int k0) {
        int rel = (k0 >> 7) ^ dc;
        const __half* src = g_Hh + ((size_t)rel * F_ + n0) * BN_ + gg * N_ + k0;
#pragma unroll
        for (int u = 0; u < 2; u++) {
            int idx = t + u * 256;
            int h = idx >> 8, rr = (idx >> 2) & 63, seg = idx & 3;
            cpa16h(stB(s, h) + rr * (KW * 2) + seg * 8, &src[(size_t)rr * BN_ + h * 32 + seg * 8]);
        }
        CP_COMMIT();
    };
    loadB(0, 0);
    loadB(1, 64);

    // alpha: 8 warps x 4 rows
#pragma unroll
    for (int rr = 0; rr < 4; rr++) {
        int rl = warp * 4 + rr;
        int d = dc * 128 + m0c + rl;
        int nd = gg * N_ + d;
        float qs0 = g_qs[nd];
        float qs1 = g_qs[BN_ + nd];
        float l[8];
        float mx = -INFINITY;
#pragma unroll
        for (int j = 0; j < 8; j++) {
            int s = j * 32 + lane;
            int rel = (s >> 7) ^ dc;
            float ksv = g_ks[rel * BN_ + gg * N_ + s];
            float qv = rel ? qs1 : qs0;
            float v = qv + ksv;
            v = v >= 0.0f ? v : 0.2f * v;
            if (s == d) v = -INFINITY;
            l[j] = v;
            mx = fmaxf(mx, v);
        }
#pragma unroll
        for (int o = 16; o; o >>= 1) mx = fmaxf(mx, __shfl_xor_sync(0xffffffffu, mx, o));
        float sum = 0.0f;
#pragma unroll
        for (int j = 0; j < 8; j++) { l[j] = expf(l[j] - mx); sum += l[j]; }
#pragma unroll
        for (int o = 16; o; o >>= 1) sum += __shfl_xor_sync(0xffffffffu, sum, o);
        float inv = 1.0f / (sum + 1e-16f);
#pragma unroll
        for (int j = 0; j < 8; j++) AL[rl * 264 + j * 32 + lane] = __float2half_rn(l[j] * inv);
    }

    float acc[4][4] = {};
    const unsigned* ALw = (const unsigned*)AL;
    for (int i = 0; i < 4; i++) {
        CP_WAIT1();
        __syncthreads();
        const unsigned* Bw = (const unsigned*)stB(i % 3, kh);
#pragma unroll
        for (int ks = 0; ks < 2; ks++) {
            int kwA = i * 32 + kh * 16 + ks * 8, kwB = ks * 8;
            unsigned a[4];
            a[0] = ALw[(wm + g) * ALW + kwA + tg];
            a[1] = ALw[(wm + g + 8) * ALW + kwA + tg];
            a[2] = ALw[(wm + g) * ALW + kwA + tg + 4];
            a[3] = ALw[(wm + g + 8) * ALW + kwA + tg + 4];
#pragma unroll
            for (int j = 0; j < 4; j++) {
                unsigned b[2];
                b[0] = Bw[(wn + j * 8 + g) * KW + kwB + tg];
                b[1] = Bw[(wn + j * 8 + g) * KW + kwB + tg + 4];
                mma16(acc[j], a, b);
            }
        }
        if (i + 2 < 4) loadB((i + 2) % 3, (i + 2) * 64);
        else CP_COMMIT();
    }

    __syncthreads();
    float* red = (float*)RAWB;
    if (kh == 1) {
        float* p = red + (wq * 32 + lane) * 16;
#pragma unroll
        for (int j = 0; j < 4; j++)
#pragma unroll
            for (int e = 0; e < 4; e++) p[j * 4 + e] = acc[j][e];
    }
    __syncthreads();
    if (kh == 0) {
        const float* p = red + (wq * 32 + lane) * 16;
#pragma unroll
        for (int j = 0; j < 4; j++)
#pragma unroll
            for (int e = 0; e < 4; e++) acc[j][e] += p[j * 4 + e];
        int node = gg * N_ + dc * 128 + m0c + wm + g;
#pragma unroll
        for (int j = 0; j < 4; j++) {
            int col = n0 + wn + j * 8 + tg * 2;
            float b0 = convb[col], b1 = convb[col + 1];
            *(__half2*)&g_m1h[(size_t)node * F_ + col] =
                __floats2half2_rn(fmaxf(acc[j][0] + b0, 0.f), fmaxf(acc[j][1] + b1, 0.f));
            *(__half2*)&g_m1h[(size_t)(node + 8) * F_ + col] =
                __floats2half2_rn(fmaxf(acc[j][2] + b0, 0.f), fmaxf(acc[j][3] + b1, 0.f));
        }
    }
}

// ---------------- lin: msg2 = [x,msg1]@lin_w^T + b (fp32 out) + BN sums ----------------
// grid (4,32) x 256, block 32x64, 2 K-groups x 4 warps (16x32 tiles), K=512
__global__ __launch_bounds__(256) void lin_k(int layer, const float* __restrict__ linb) {
    int m0 = blockIdx.y * 32, n0 = blockIdx.x * 64;
    __shared__ __align__(16) unsigned char RAW[3 * 15360];
    int t = threadIdx.x, lane = t & 31, warp = t >> 5;
    int kh = warp >> 2, wq = warp & 3;
    int wm = (wq >> 1) * 16, wn = (wq & 1) * 32;
    int g = lane >> 2, tg = lane & 3;
    const __half* lwp = g_lwh + (size_t)layer * F_ * 2 * F_;

    auto stA = [&](int s, int h) { return (__half*)(RAW + s * 15360 + h * 2560); };
    auto stB = [&](int s, int h) { return (__half*)(RAW + s * 15360 + 5120 + h * 5120); };
    auto loadst = [&](int s, int k0) {
        {
            int h = t >> 7, rr = (t >> 2) & 31, seg = t & 3;
            const __half* Ab = (k0 < F_) ? &g_xh[(m0 + rr) * F_ + k0 + h * 32 + seg * 8]
                                         : &g_m1h[(m0 + rr) * F_ + (k0 - F_) + h * 32 + seg * 8];
            cpa16h(stA(s, h) + rr * (KW * 2) + seg * 8, Ab);
        }
#pragma unroll
        for (int u = 0; u < 2; u++) {
            int idx = t + u * 256;
            int h = idx >> 8, rr = (idx >> 2) & 63, seg = idx & 3;
            cpa16h(stB(s, h) + rr * (KW * 2) + seg * 8,
                   &lwp[(size_t)(n0 + rr) * 512 + k0 + h * 32 + seg * 8]);
        }
        CP_COMMIT();
    };

    float acc[4][4] = {};
    loadst(0, 0);
    loadst(1, 64);
    for (int i = 0; i < 8; i++) {
        CP_WAIT1();
        __syncthreads();
        const unsigned* Aw = (const unsigned*)stA(i % 3, kh);
        const unsigned* Bw = (const unsigned*)stB(i % 3, kh);
#pragma unroll
        for (int ks = 0; ks < 2; ks++) {
            int kw = ks * 8;
            unsigned a[4];
            a[0] = Aw[(wm + g) * KW + kw + tg];
            a[1] = Aw[(wm + g + 8) * KW + kw + tg];
            a[2] = Aw[(wm + g) * KW + kw + tg + 4];
            a[3] = Aw[(wm + g + 8) * KW + kw + tg + 4];
#pragma unroll
            for (int j = 0; j < 4; j++) {
                unsigned b[2];
                b[0] = Bw[(wn + j * 8 + g) * KW + kw + tg];
                b[1] = Bw[(wn + j * 8 + g) * KW + kw + tg + 4];
                mma16(acc[j], a, b);
            }
        }
        if (i + 2 < 8) loadst((i + 2) % 3, (i + 2) * 64);
        else CP_COMMIT();
    }

    __syncthreads();
    float* red = (float*)RAW;
    if (kh == 1) {
        float* p = red + (wq * 32 + lane) * 16;
#pragma unroll
        for (int j = 0; j < 4; j++)
#pragma unroll
            for (int e = 0; e < 4; e++) p[j * 4 + e] = acc[j][e];
    }
    __syncthreads();
    if (kh == 0) {
        const float* p = red + (wq * 32 + lane) * 16;
#pragma unroll
        for (int j = 0; j < 4; j++)
#pragma unroll
            for (int e = 0; e < 4; e++) acc[j][e] += p[j * 4 + e];

        int row = m0 + wm + g;
        float s0[4], s1[4], q0[4], q1[4];
#pragma unroll
        for (int j = 0; j < 4; j++) {
            int col = n0 + wn + j * 8 + tg * 2;
            float b0 = linb[col], b1 = linb[col + 1];
            float v0 = acc[j][0] + b0, v1 = acc[j][1] + b1;
            float v2 = acc[j][2] + b0, v3 = acc[j][3] + b1;
            *(float2*)&g_msg2[(size_t)row * F_ + col] = make_float2(v0, v1);
            *(float2*)&g_msg2[(size_t)(row + 8) * F_ + col] = make_float2(v2, v3);
            s0[j] = v0 + v2; s1[j] = v1 + v3;
            q0[j] = v0 * v0 + v2 * v2; q1[j] = v1 * v1 + v3 * v3;
        }
#pragma unroll
        for (int o = 4; o < 32; o <<= 1)
#pragma unroll
            for (int j = 0; j < 4; j++) {
                s0[j] += __shfl_xor_sync(0xffffffffu, s0[j], o);
                s1[j] += __shfl_xor_sync(0xffffffffu, s1[j], o);
                q0[j] += __shfl_xor_sync(0xffffffffu, q0[j], o);
                q1[j] += __shfl_xor_sync(0xffffffffu, q1[j], o);
            }
        if (g == 0) {
#pragma unroll
            for (int j = 0; j < 4; j++) {
                int col = n0 + wn + j * 8 + tg * 2;
                atomicAdd(&g_sum[col], s0[j]);
                atomicAdd(&g_sum[col + 1], s1[j]);
                atomicAdd(&g_sum2[col], q0[j]);
                atomicAdd(&g_sum2[col + 1], q1[j]);
            }
        }
    }
}

// ---------------- batchnorm apply (computes mu/rstd inline) + residual ----------------
__global__ void bn_apply(const float* __restrict__ bw, const float* __restrict__ bb) {
    int c = threadIdx.x;
    float mu = g_sum[c] * (1.0f / BN_);
    float var = g_sum2[c] * (1.0f / BN_) - mu * mu;
    float rstd = rsqrtf(var + 1e-5f);
    int idx = blockIdx.x * F_ + c;
    float v = g_x[idx] + bw[c] * (g_msg2[idx] - mu) * rstd + bb[c];
    g_x[idx] = v;
    g_xh[idx] = __float2half_rn(v);
    if (blockIdx.x < 16) {
        int zi = blockIdx.x * 256 + c;
        if (zi < 2048) g_qs[zi] = 0.f;
        else           g_ks[zi - 2048] = 0.f;
    }
}

// ---------------- unpack ----------------
__global__ void unpack_kernel(float* __restrict__ out) {
    int b = blockIdx.x >> 8;
    int n = blockIdx.x & 255;
    int f = threadIdx.x;
    float v = g_x[(b * N_ + n) * F_ + f];
    if (n < N0_) out[(b * F_ + f) * N0_ + n] = v;
    else         out[B_ * F_ * N0_ + (b * F_ + f) * N0_ + (n - N0_)] = v;
}

// ---------------- host ----------------
extern "C" void kernel_launch(void* const* d_in, const int* in_sizes, int n_in,
                              void* d_out, int out_size) {
    const float* desc0  = (const float*)d_in[0];
    const float* desc1  = (const float*)d_in[1];
    const float* conv_w = (const float*)d_in[2];
    const float* conv_q = (const float*)d_in[3];
    const float* conv_k = (const float*)d_in[4];
    const float* conv_b = (const float*)d_in[5];
    const float* lin_w  = (const float*)d_in[6];
    const float* lin_b  = (const float*)d_in[7];
    const float* bn_w   = (const float*)d_in[8];
    const float* bn_b   = (const float*)d_in[9];
    float* out = (float*)d_out;

    cudaFuncSetAttribute(gemm_H_k, cudaFuncAttributeMaxDynamicSharedMemorySize, 61440);

    prep_kernel<<<2176, 256>>>(desc0, desc1, conv_w, lin_w);

    for (int i = 0; i < L_; i++) {
        gemm_H_k<<<dim3(4, 16, 2), 256, 61440>>>(i, conv_q + i * F_, conv_k + i * F_);
        attn_k<<<dim3(4, 4, 8), 256>>>(conv_b + i * F_);
        lin_k<<<dim3(4, 32), 256>>>(i, lin_b + i * F_);
        bn_apply<<<BN_, F_>>>(bn_w + i * F_, bn_b + i * F_);
    }

    unpack_kernel<<<BN_, F_>>>(out);
}